// round 2
// baseline (speedup 1.0000x reference)
#include <cuda_runtime.h>
#include <cstdint>

static constexpr int NB = 8;
static constexpr int NC = 256;
static constexpr int NH = 160;
static constexpr int NW = 160;
static constexpr int NHW = NH * NW;           // 25600
static constexpr float BN_EPS = 1e-5f;

// ---------------- scratch (static device globals; no allocations) ----------
__device__ float g_xal[(size_t)NB * NC * NHW];   // aligned+BN+SiLU activations
__device__ float g_gsum[NB * NC];
__device__ float g_gmax[NB * NC];
__device__ float g_lsum[NB * NC * 16];
__device__ float g_ca[NB * NC];
__device__ float g_sf[NB * 2 * NHW];
__device__ float g_o1[NB * 16 * NHW];
__device__ float g_sampled[NB * 2 * NHW];
__device__ float g_sa[NB * NHW];
__device__ float g_wavg[2 * 16 * 9];
__device__ float g_bavg[2];

__device__ __forceinline__ float sigmoidf_(float x) {
    return 1.f / (1.f + __expf(-x));
}

// ---------------------------------------------------------------------------
// Kernel 1: 1x1 conv (GEMM 256x256 x 25600 per batch) + BN + SiLU -> g_xal
// Classic 128x128x8 SGEMM, 256 threads, 8x8 per thread.
// ---------------------------------------------------------------------------
__global__ __launch_bounds__(256) void align_gemm_kernel(
    const float* __restrict__ Wmat,   // [256,256]
    const float* __restrict__ X,      // [8,256,25600]
    const float* __restrict__ bn_g, const float* __restrict__ bn_b,
    const float* __restrict__ bn_m, const float* __restrict__ bn_v)
{
    constexpr int BM = 128, BN_ = 128, BK = 8, TM = 8, TN = 8;
    const int b = blockIdx.z;
    const int pBase = blockIdx.x * BN_;
    const int coBase = blockIdx.y * BM;
    const float* Xb = X + (size_t)b * NC * NHW;
    float* Yb = g_xal + (size_t)b * NC * NHW;

    __shared__ float As[BK][BM];
    __shared__ float Bs[BK][BN_];

    const int tid = threadIdx.x;
    const int aRow = tid >> 1;            // 0..127
    const int aCol = (tid & 1) * 4;       // 0 or 4
    const int bRow = tid >> 5;            // 0..7
    const int bCol = (tid & 31) * 4;      // 0..124
    const int tr = tid / 16;              // 0..15
    const int tc = tid % 16;              // 0..15

    float acc[TM][TN];
    #pragma unroll
    for (int i = 0; i < TM; i++)
        #pragma unroll
        for (int j = 0; j < TN; j++) acc[i][j] = 0.f;

    for (int k0 = 0; k0 < NC; k0 += BK) {
        float4 av = *reinterpret_cast<const float4*>(
            &Wmat[(coBase + aRow) * NC + k0 + aCol]);
        As[aCol + 0][aRow] = av.x;
        As[aCol + 1][aRow] = av.y;
        As[aCol + 2][aRow] = av.z;
        As[aCol + 3][aRow] = av.w;
        *reinterpret_cast<float4*>(&Bs[bRow][bCol]) =
            *reinterpret_cast<const float4*>(
                &Xb[(size_t)(k0 + bRow) * NHW + pBase + bCol]);
        __syncthreads();
        #pragma unroll
        for (int k = 0; k < BK; k++) {
            float ar[TM], br[TN];
            #pragma unroll
            for (int i = 0; i < TM; i++) ar[i] = As[k][tr * TM + i];
            #pragma unroll
            for (int j = 0; j < TN; j++) br[j] = Bs[k][tc * TN + j];
            #pragma unroll
            for (int i = 0; i < TM; i++)
                #pragma unroll
                for (int j = 0; j < TN; j++) acc[i][j] += ar[i] * br[j];
        }
        __syncthreads();
    }

    #pragma unroll
    for (int i = 0; i < TM; i++) {
        const int co = coBase + tr * TM + i;
        const float sc = bn_g[co] * rsqrtf(bn_v[co] + BN_EPS);
        const float tb = bn_b[co] - bn_m[co] * sc;
        float4 r0, r1;
        float tmp[TN];
        #pragma unroll
        for (int j = 0; j < TN; j++) {
            float y = acc[i][j] * sc + tb;
            tmp[j] = y * sigmoidf_(y);       // SiLU
        }
        r0 = make_float4(tmp[0], tmp[1], tmp[2], tmp[3]);
        r1 = make_float4(tmp[4], tmp[5], tmp[6], tmp[7]);
        float* dst = &Yb[(size_t)co * NHW + pBase + tc * TN];
        *reinterpret_cast<float4*>(dst) = r0;
        *reinterpret_cast<float4*>(dst + 4) = r1;
    }
}

// ---------------------------------------------------------------------------
// Kernel 2: per-(b,c) global sum/max + 4x4 local pool sums
// One block per (b,c), 160 threads (one per column).
// ---------------------------------------------------------------------------
__global__ __launch_bounds__(160) void pool_kernel() {
    const int bc = blockIdx.x;                  // 0..2047
    const float* p = g_xal + (size_t)bc * NHW;
    const int w = threadIdx.x;                  // 0..159
    const int gxc = w / 40;

    __shared__ float shl[16];
    __shared__ float ws[5], wm[5];
    if (threadIdx.x < 16) shl[threadIdx.x] = 0.f;
    __syncthreads();

    float s = 0.f, mx = -1e30f;
    #pragma unroll
    for (int gy = 0; gy < 4; gy++) {
        float bs = 0.f;
        for (int h = gy * 40; h < gy * 40 + 40; h++) {
            float v = p[h * NW + w];
            bs += v;
            mx = fmaxf(mx, v);
        }
        s += bs;
        atomicAdd(&shl[gy * 4 + gxc], bs);
    }
    // warp reduce
    #pragma unroll
    for (int o = 16; o > 0; o >>= 1) {
        s += __shfl_down_sync(0xffffffffu, s, o);
        mx = fmaxf(mx, __shfl_down_sync(0xffffffffu, mx, o));
    }
    const int lane = threadIdx.x & 31, wid = threadIdx.x >> 5;
    if (lane == 0) { ws[wid] = s; wm[wid] = mx; }
    __syncthreads();
    if (threadIdx.x == 0) {
        float S = 0.f, M = -1e30f;
        #pragma unroll
        for (int i = 0; i < 5; i++) { S += ws[i]; M = fmaxf(M, wm[i]); }
        g_gsum[bc] = S;
        g_gmax[bc] = M;
    }
    if (threadIdx.x < 16) g_lsum[bc * 16 + threadIdx.x] = shl[threadIdx.x];
}

// ---------------------------------------------------------------------------
// Kernel 3: pre-average offset conv2 weights over the 49 output taps
// ---------------------------------------------------------------------------
__global__ void prep_kernel(const float* __restrict__ off_w2,
                            const float* __restrict__ off_b2) {
    const int i = threadIdx.x;
    if (i < 288) {
        const int d = i / 144, rest = i % 144;
        float s = 0.f;
        for (int j = 0; j < 49; j++) s += off_w2[(d * 49 + j) * 144 + rest];
        g_wavg[i] = s * (1.f / 49.f);
    }
    if (i < 2) {
        float s = 0.f;
        for (int j = 0; j < 49; j++) s += off_b2[i * 49 + j];
        g_bavg[i] = s * (1.f / 49.f);
    }
}

// ---------------------------------------------------------------------------
// Kernel 4: channel attention -> g_ca[b, c]
// One block per batch, 256 threads.
// ---------------------------------------------------------------------------
__global__ __launch_bounds__(256) void ca_kernel(
    const float* __restrict__ mlp_w1, const float* __restrict__ mlp_w2,
    const float* __restrict__ loc_w1, const float* __restrict__ loc_w2,
    const float* __restrict__ fusion_w)
{
    const int b = blockIdx.x, tid = threadIdx.x;
    __shared__ float avg[256], mxv[256], loc[16][256];
    __shared__ float h1[32], hcell[16][16], hbar[16];

    avg[tid] = g_gsum[b * NC + tid] * (1.f / (float)NHW);
    mxv[tid] = g_gmax[b * NC + tid];
    #pragma unroll
    for (int cell = 0; cell < 16; cell++)
        loc[cell][tid] = g_lsum[(b * NC + tid) * 16 + cell] * (1.f / 1600.f);
    __syncthreads();

    if (tid < 32) {
        const int m = tid & 15;
        const float* src = (tid < 16) ? avg : mxv;
        float acc = 0.f;
        for (int c = 0; c < NC; c++) acc += mlp_w1[m * NC + c] * src[c];
        h1[tid] = fmaxf(acc, 0.f);
    }
    {
        const int cell = tid >> 4, m = tid & 15;
        float acc = 0.f;
        for (int c = 0; c < NC; c++) acc += loc_w1[m * NC + c] * loc[cell][c];
        hcell[cell][m] = fmaxf(acc, 0.f);
    }
    __syncthreads();
    if (tid < 16) {
        float s = 0.f;
        #pragma unroll
        for (int cell = 0; cell < 16; cell++) s += hcell[cell][tid];
        hbar[tid] = s * (1.f / 16.f);
    }
    __syncthreads();

    float ga = 0.f, la = 0.f;
    #pragma unroll
    for (int m = 0; m < 16; m++) {
        ga += mlp_w2[tid * 16 + m] * (h1[m] + h1[16 + m]);
        la += loc_w2[tid * 16 + m] * hbar[m];
    }
    const float alpha = sigmoidf_(fusion_w[0]);
    g_ca[b * NC + tid] = sigmoidf_(alpha * ga + (1.f - alpha) * la);
}

// ---------------------------------------------------------------------------
// Kernel 5: sf = [mean_c(ca*x), max_c(ca*x)]   (x = aligned activations)
// ---------------------------------------------------------------------------
__global__ __launch_bounds__(256) void sf_kernel() {
    const int b = blockIdx.y;
    const int p = blockIdx.x * blockDim.x + threadIdx.x;
    const float* xb = g_xal + (size_t)b * NC * NHW + p;
    const float* cab = g_ca + b * NC;
    float s = 0.f, mx = -1e30f;
    #pragma unroll 4
    for (int c = 0; c < NC; c++) {
        float v = cab[c] * xb[(size_t)c * NHW];
        s += v;
        mx = fmaxf(mx, v);
    }
    g_sf[(size_t)b * 2 * NHW + p] = s * (1.f / (float)NC);
    g_sf[(size_t)b * 2 * NHW + NHW + p] = mx;
}

// ---------------------------------------------------------------------------
// Kernel 6: offset conv1: 3x3, 2->16 + BN + ReLU
// ---------------------------------------------------------------------------
__global__ __launch_bounds__(256) void off1_kernel(
    const float* __restrict__ w1, const float* __restrict__ gg,
    const float* __restrict__ bt, const float* __restrict__ mm,
    const float* __restrict__ vv)
{
    const int p = blockIdx.x * blockDim.x + threadIdx.x;
    const int co = blockIdx.y, b = blockIdx.z;
    const int h = p / NW, w = p % NW;
    const float* sfb = g_sf + (size_t)b * 2 * NHW;
    float acc = 0.f;
    #pragma unroll
    for (int ci = 0; ci < 2; ci++) {
        #pragma unroll
        for (int ky = 0; ky < 3; ky++) {
            const int hy = h + ky - 1;
            if (hy < 0 || hy >= NH) continue;
            #pragma unroll
            for (int kx = 0; kx < 3; kx++) {
                const int wx = w + kx - 1;
                if (wx < 0 || wx >= NW) continue;
                acc += w1[((co * 2 + ci) * 3 + ky) * 3 + kx] *
                       sfb[ci * NHW + hy * NW + wx];
            }
        }
    }
    const float sc = gg[co] * rsqrtf(vv[co] + BN_EPS);
    const float tb = bt[co] - mm[co] * sc;
    g_o1[((size_t)b * 16 + co) * NHW + p] = fmaxf(acc * sc + tb, 0.f);
}

// ---------------------------------------------------------------------------
// Kernel 7: averaged offset conv2 (3x3, 16->2) + tanh*0.5 + base grid +
//           clip + bilinear grid-sample of sf -> g_sampled
// ---------------------------------------------------------------------------
__global__ __launch_bounds__(256) void off2_sample_kernel() {
    const int b = blockIdx.y;
    const int p = blockIdx.x * blockDim.x + threadIdx.x;
    const int h = p / NW, w = p % NW;
    const float* o1b = g_o1 + (size_t)b * 16 * NHW;

    float off[2];
    #pragma unroll
    for (int d = 0; d < 2; d++) {
        float acc = g_bavg[d];
        for (int ci = 0; ci < 16; ci++) {
            #pragma unroll
            for (int ky = 0; ky < 3; ky++) {
                const int hy = h + ky - 1;
                if (hy < 0 || hy >= NH) continue;
                #pragma unroll
                for (int kx = 0; kx < 3; kx++) {
                    const int wx = w + kx - 1;
                    if (wx < 0 || wx >= NW) continue;
                    acc += g_wavg[(d * 16 + ci) * 9 + ky * 3 + kx] *
                           o1b[(size_t)ci * NHW + hy * NW + wx];
                }
            }
        }
        off[d] = tanhf(acc) * 0.5f;
    }

    const float bx = -1.f + 2.f * (float)w / 159.f;
    const float by = -1.f + 2.f * (float)h / 159.f;
    const float gx = fminf(fmaxf(bx + off[0], -1.f), 1.f);
    const float gy = fminf(fmaxf(by + off[1], -1.f), 1.f);

    const float fx = (gx + 1.f) * ((float)NW * 0.5f) - 0.5f;
    const float fy = (gy + 1.f) * ((float)NH * 0.5f) - 0.5f;
    const float x0f = floorf(fx), y0f = floorf(fy);
    const int x0 = (int)x0f, y0 = (int)y0f;
    const float wx = fx - x0f, wy = fy - y0f;

    const float* sfb = g_sf + (size_t)b * 2 * NHW;
    float out0 = 0.f, out1 = 0.f;
    #pragma unroll
    for (int dy = 0; dy < 2; dy++) {
        const int yy = y0 + dy;
        if (yy < 0 || yy >= NH) continue;
        const float wgy = dy ? wy : (1.f - wy);
        #pragma unroll
        for (int dx = 0; dx < 2; dx++) {
            const int xx = x0 + dx;
            if (xx < 0 || xx >= NW) continue;
            const float wt = wgy * (dx ? wx : (1.f - wx));
            out0 += wt * sfb[yy * NW + xx];
            out1 += wt * sfb[NHW + yy * NW + xx];
        }
    }
    g_sampled[(size_t)b * 2 * NHW + p] = out0;
    g_sampled[(size_t)b * 2 * NHW + NHW + p] = out1;
}

// ---------------------------------------------------------------------------
// Kernel 8: 7x7 conv (2->1) over sampled + sigmoid -> g_sa
// ---------------------------------------------------------------------------
__global__ __launch_bounds__(256) void sa_kernel(const float* __restrict__ attn_w) {
    const int b = blockIdx.y;
    const int p = blockIdx.x * blockDim.x + threadIdx.x;
    const int h = p / NW, w = p % NW;
    const float* sm = g_sampled + (size_t)b * 2 * NHW;
    float acc = 0.f;
    #pragma unroll
    for (int ci = 0; ci < 2; ci++) {
        #pragma unroll
        for (int ky = 0; ky < 7; ky++) {
            const int hy = h + ky - 3;
            if (hy < 0 || hy >= NH) continue;
            #pragma unroll
            for (int kx = 0; kx < 7; kx++) {
                const int wx = w + kx - 3;
                if (wx < 0 || wx >= NW) continue;
                acc += attn_w[(ci * 7 + ky) * 7 + kx] *
                       sm[ci * NHW + hy * NW + wx];
            }
        }
    }
    g_sa[b * NHW + p] = sigmoidf_(acc);
}

// ---------------------------------------------------------------------------
// Kernel 9: out = sa * ca * x_aligned   (vectorized float4)
// ---------------------------------------------------------------------------
__global__ __launch_bounds__(256) void final_kernel(float* __restrict__ out) {
    const unsigned idx4 = blockIdx.x * blockDim.x + threadIdx.x;
    const unsigned total4 = (unsigned)NB * NC * NHW / 4;
    if (idx4 >= total4) return;
    const unsigned e = idx4 * 4;
    const unsigned p = e % NHW;
    const unsigned c = (e / NHW) % NC;
    const unsigned b = e / (NHW * NC);
    const float4 xv = *reinterpret_cast<const float4*>(&g_xal[e]);
    const float4 sav = *reinterpret_cast<const float4*>(&g_sa[b * NHW + p]);
    const float cc = g_ca[b * NC + c];
    float4 r;
    r.x = xv.x * sav.x * cc;
    r.y = xv.y * sav.y * cc;
    r.z = xv.z * sav.z * cc;
    r.w = xv.w * sav.w * cc;
    *reinterpret_cast<float4*>(&out[e]) = r;
}

// ---------------------------------------------------------------------------
extern "C" void kernel_launch(void* const* d_in, const int* in_sizes, int n_in,
                              void* d_out, int out_size) {
    const float* x       = (const float*)d_in[0];
    const float* align_w = (const float*)d_in[1];
    const float* align_g = (const float*)d_in[2];
    const float* align_b = (const float*)d_in[3];
    const float* align_m = (const float*)d_in[4];
    const float* align_v = (const float*)d_in[5];
    const float* mlp_w1  = (const float*)d_in[6];
    const float* mlp_w2  = (const float*)d_in[7];
    const float* loc_w1  = (const float*)d_in[8];
    const float* loc_w2  = (const float*)d_in[9];
    const float* fusion  = (const float*)d_in[10];
    const float* off_w1  = (const float*)d_in[11];
    const float* off_g   = (const float*)d_in[12];
    const float* off_bt  = (const float*)d_in[13];
    const float* off_m   = (const float*)d_in[14];
    const float* off_v   = (const float*)d_in[15];
    const float* off_w2  = (const float*)d_in[16];
    const float* off_b2  = (const float*)d_in[17];
    const float* attn_w  = (const float*)d_in[18];
    float* out = (float*)d_out;

    // 1. align GEMM + BN + SiLU
    dim3 gGemm(NHW / 128, NC / 128, NB);
    align_gemm_kernel<<<gGemm, 256>>>(align_w, x, align_g, align_b, align_m, align_v);

    // 2. channel pools
    pool_kernel<<<NB * NC, 160>>>();

    // 3. averaged offset-conv2 weights (independent)
    prep_kernel<<<1, 288>>>(off_w2, off_b2);

    // 4. channel attention
    ca_kernel<<<NB, 256>>>(mlp_w1, mlp_w2, loc_w1, loc_w2, fusion);

    // 5. spatial features (mean/max over channels of ca*x)
    dim3 gPix(NHW / 256, NB);
    sf_kernel<<<gPix, 256>>>();

    // 6. offset conv1
    dim3 gOff1(NHW / 256, 16, NB);
    off1_kernel<<<gOff1, 256>>>(off_w1, off_g, off_bt, off_m, off_v);

    // 7. offset conv2 (averaged) + grid sample
    off2_sample_kernel<<<gPix, 256>>>();

    // 8. 7x7 spatial attention conv + sigmoid
    sa_kernel<<<gPix, 256>>>(attn_w);

    // 9. final elementwise product
    const unsigned total4 = (unsigned)NB * NC * NHW / 4;
    final_kernel<<<(total4 + 255) / 256, 256>>>(out);
}

// round 3
// speedup vs baseline: 1.3619x; 1.3619x over previous
#include <cuda_runtime.h>
#include <cuda_bf16.h>
#include <cstdint>

static constexpr int NB = 8;
static constexpr int NC = 256;
static constexpr int NH = 160;
static constexpr int NW = 160;
static constexpr int NHW = NH * NW;           // 25600
static constexpr float BN_EPS = 1e-5f;

// ---------------- scratch (static device globals) --------------------------
__device__ float g_xal[(size_t)NB * NC * NHW];
__device__ uint32_t g_wph[NC * 128];     // packed bf16x2 (k-pairs) scaled W, hi
__device__ uint32_t g_wpl[NC * 128];     // lo residual
__device__ float g_bias[NC];
__device__ float g_gsum[NB * NC];
__device__ float g_gmax[NB * NC];
__device__ float g_lsum[NB * NC * 16];
__device__ float g_ca[NB * NC];
__device__ float g_sf[NB * 2 * NHW];
__device__ float g_o1[NB * 16 * NHW];
__device__ float g_sampled[NB * 2 * NHW];
__device__ float g_sa[NB * NHW];
__device__ float g_wavg[2 * 16 * 9];
__device__ float g_bavg[2];

__device__ __forceinline__ float sigmoidf_(float x) {
    return 1.f / (1.f + __expf(-x));
}
__device__ __forceinline__ uint32_t packbf(float a, float b) {
    __nv_bfloat162 t = __floats2bfloat162_rn(a, b);   // low = a
    return *reinterpret_cast<uint32_t*>(&t);
}
__device__ __forceinline__ void mma16816(float* c, const uint32_t* a,
                                         uint32_t b0, uint32_t b1) {
    asm volatile(
        "mma.sync.aligned.m16n8k16.row.col.f32.bf16.bf16.f32 "
        "{%0,%1,%2,%3}, {%4,%5,%6,%7}, {%8,%9}, {%0,%1,%2,%3};"
        : "+f"(c[0]), "+f"(c[1]), "+f"(c[2]), "+f"(c[3])
        : "r"(a[0]), "r"(a[1]), "r"(a[2]), "r"(a[3]), "r"(b0), "r"(b1));
}

// ---------------------------------------------------------------------------
// Kernel 0: pack BN-scaled weights into split-bf16 k-pairs
// ---------------------------------------------------------------------------
__global__ __launch_bounds__(256) void wpack_kernel(
    const float* __restrict__ w, const float* __restrict__ g,
    const float* __restrict__ bb, const float* __restrict__ m,
    const float* __restrict__ v)
{
    const int id = blockIdx.x * 256 + threadIdx.x;   // 0..32767
    const int co = id >> 7, kp = id & 127;
    const float sc = g[co] * rsqrtf(v[co] + BN_EPS);
    const float w0 = w[co * 256 + 2 * kp] * sc;
    const float w1 = w[co * 256 + 2 * kp + 1] * sc;
    const float h0 = __bfloat162float(__float2bfloat16(w0));
    const float h1 = __bfloat162float(__float2bfloat16(w1));
    g_wph[co * 128 + kp] = packbf(h0, h1);
    g_wpl[co * 128 + kp] = packbf(w0 - h0, w1 - h1);
    if (kp == 0) g_bias[co] = bb[co] - m[co] * sc;
}

// ---------------------------------------------------------------------------
// Kernel 1: tensor-core GEMM (128 co x 128 pix per CTA, K=256, split bf16)
//           + bias + SiLU epilogue -> g_xal
// ---------------------------------------------------------------------------
__global__ __launch_bounds__(256) void gemm_kernel(const float* __restrict__ X)
{
    __shared__ uint32_t sWh[128 * 20], sWl[128 * 20];
    __shared__ uint32_t sXh[128 * 20], sXl[128 * 20];

    const int tile = blockIdx.x, half = blockIdx.y, b = blockIdx.z;
    const int tileBase = tile * 128;
    const int t = threadIdx.x, lane = t & 31, warp = t >> 5;
    const int warpM = warp >> 1, warpN = warp & 1;
    const int q = lane >> 2, r = lane & 3;
    const float* Xb = X + (size_t)b * NC * NHW + tileBase;
    const int wRow = t >> 1, wHf = (t & 1) * 8;
    const int kp = t & 15, pg = t >> 4;

    float acc[2][8][4];
    #pragma unroll
    for (int i = 0; i < 2; i++)
        #pragma unroll
        for (int j = 0; j < 8; j++)
            #pragma unroll
            for (int k = 0; k < 4; k++) acc[i][j][k] = 0.f;

    for (int c = 0; c < 8; c++) {
        // ---- stage W chunk (co rows, k pairs c*16..c*16+15) ----
        {
            const uint32_t* sh = &g_wph[(size_t)(half * 128 + wRow) * 128 + c * 16 + wHf];
            const uint32_t* sl = &g_wpl[(size_t)(half * 128 + wRow) * 128 + c * 16 + wHf];
            *(uint4*)&sWh[wRow * 20 + wHf]     = *(const uint4*)sh;
            *(uint4*)&sWh[wRow * 20 + wHf + 4] = *(const uint4*)(sh + 4);
            *(uint4*)&sWl[wRow * 20 + wHf]     = *(const uint4*)sl;
            *(uint4*)&sWl[wRow * 20 + wHf + 4] = *(const uint4*)(sl + 4);
        }
        // ---- stage X chunk, transpose to [pixel][kpair], split bf16 ----
        {
            const float* x0 = Xb + (size_t)(c * 32 + 2 * kp) * NHW + pg * 8;
            const float* x1 = x0 + NHW;
            float4 a0 = *(const float4*)x0, b0 = *(const float4*)(x0 + 4);
            float4 a1 = *(const float4*)x1, b1 = *(const float4*)(x1 + 4);
            float e0[8] = {a0.x, a0.y, a0.z, a0.w, b0.x, b0.y, b0.z, b0.w};
            float e1[8] = {a1.x, a1.y, a1.z, a1.w, b1.x, b1.y, b1.z, b1.w};
            #pragma unroll
            for (int j = 0; j < 8; j++) {
                const float h0 = __bfloat162float(__float2bfloat16(e0[j]));
                const float h1 = __bfloat162float(__float2bfloat16(e1[j]));
                sXh[(pg * 8 + j) * 20 + kp] = packbf(h0, h1);
                sXl[(pg * 8 + j) * 20 + kp] = packbf(e0[j] - h0, e1[j] - h1);
            }
        }
        __syncthreads();
        #pragma unroll
        for (int ks = 0; ks < 2; ks++) {
            uint32_t ah[2][4], al[2][4];
            #pragma unroll
            for (int mt = 0; mt < 2; mt++) {
                const int base = (warpM * 32 + mt * 16 + q) * 20 + ks * 8;
                ah[mt][0] = sWh[base + r];       ah[mt][1] = sWh[base + 160 + r];
                ah[mt][2] = sWh[base + 4 + r];   ah[mt][3] = sWh[base + 164 + r];
                al[mt][0] = sWl[base + r];       al[mt][1] = sWl[base + 160 + r];
                al[mt][2] = sWl[base + 4 + r];   al[mt][3] = sWl[base + 164 + r];
            }
            #pragma unroll
            for (int nt = 0; nt < 8; nt++) {
                const int xb = (warpN * 64 + nt * 8 + q) * 20 + ks * 8;
                const uint32_t bh0 = sXh[xb + r], bh1 = sXh[xb + 4 + r];
                const uint32_t bl0 = sXl[xb + r], bl1 = sXl[xb + 4 + r];
                #pragma unroll
                for (int mt = 0; mt < 2; mt++) {
                    mma16816(acc[mt][nt], ah[mt], bh0, bh1);
                    mma16816(acc[mt][nt], al[mt], bh0, bh1);
                    mma16816(acc[mt][nt], ah[mt], bl0, bl1);
                }
            }
        }
        __syncthreads();
    }

    // ---- epilogue: bias + SiLU + store ----
    #pragma unroll
    for (int mt = 0; mt < 2; mt++) {
        const int co0 = half * 128 + warpM * 32 + mt * 16 + q;
        const int co1 = co0 + 8;
        const float tb0 = g_bias[co0], tb1 = g_bias[co1];
        float* y0 = g_xal + ((size_t)b * NC + co0) * NHW + tileBase;
        float* y1 = g_xal + ((size_t)b * NC + co1) * NHW + tileBase;
        #pragma unroll
        for (int nt = 0; nt < 8; nt++) {
            const int pix = warpN * 64 + nt * 8 + 2 * r;
            float v0 = acc[mt][nt][0] + tb0, v1 = acc[mt][nt][1] + tb0;
            float v2 = acc[mt][nt][2] + tb1, v3 = acc[mt][nt][3] + tb1;
            *(float2*)&y0[pix] = make_float2(v0 * sigmoidf_(v0), v1 * sigmoidf_(v1));
            *(float2*)&y1[pix] = make_float2(v2 * sigmoidf_(v2), v3 * sigmoidf_(v3));
        }
    }
}

// ---------------------------------------------------------------------------
// Kernel 2: per-(b,c) global sum/max + 4x4 local pool sums
// ---------------------------------------------------------------------------
__global__ __launch_bounds__(160) void pool_kernel() {
    const int bc = blockIdx.x;
    const float* p = g_xal + (size_t)bc * NHW;
    const int w = threadIdx.x;
    const int gxc = w / 40;

    __shared__ float shl[16];
    __shared__ float ws[5], wm[5];
    if (threadIdx.x < 16) shl[threadIdx.x] = 0.f;
    __syncthreads();

    float s = 0.f, mx = -1e30f;
    #pragma unroll
    for (int gy = 0; gy < 4; gy++) {
        float bs = 0.f;
        for (int h = gy * 40; h < gy * 40 + 40; h++) {
            float v = p[h * NW + w];
            bs += v;
            mx = fmaxf(mx, v);
        }
        s += bs;
        atomicAdd(&shl[gy * 4 + gxc], bs);
    }
    #pragma unroll
    for (int o = 16; o > 0; o >>= 1) {
        s += __shfl_down_sync(0xffffffffu, s, o);
        mx = fmaxf(mx, __shfl_down_sync(0xffffffffu, mx, o));
    }
    const int lane = threadIdx.x & 31, wid = threadIdx.x >> 5;
    if (lane == 0) { ws[wid] = s; wm[wid] = mx; }
    __syncthreads();
    if (threadIdx.x == 0) {
        float S = 0.f, M = -1e30f;
        #pragma unroll
        for (int i = 0; i < 5; i++) { S += ws[i]; M = fmaxf(M, wm[i]); }
        g_gsum[bc] = S;
        g_gmax[bc] = M;
    }
    if (threadIdx.x < 16) g_lsum[bc * 16 + threadIdx.x] = shl[threadIdx.x];
}

// ---------------------------------------------------------------------------
// Kernel 3: pre-average offset conv2 weights over the 49 output taps
// ---------------------------------------------------------------------------
__global__ void prep_kernel(const float* __restrict__ off_w2,
                            const float* __restrict__ off_b2) {
    const int i = threadIdx.x;
    if (i < 288) {
        const int d = i / 144, rest = i % 144;
        float s = 0.f;
        for (int j = 0; j < 49; j++) s += off_w2[(d * 49 + j) * 144 + rest];
        g_wavg[i] = s * (1.f / 49.f);
    }
    if (i < 2) {
        float s = 0.f;
        for (int j = 0; j < 49; j++) s += off_b2[i * 49 + j];
        g_bavg[i] = s * (1.f / 49.f);
    }
}

// ---------------------------------------------------------------------------
// Kernel 4: channel attention -> g_ca   (parallel partial dots)
// ---------------------------------------------------------------------------
__global__ __launch_bounds__(256) void ca_kernel(
    const float* __restrict__ mlp_w1, const float* __restrict__ mlp_w2,
    const float* __restrict__ loc_w1, const float* __restrict__ loc_w2,
    const float* __restrict__ fusion_w)
{
    const int b = blockIdx.x, tid = threadIdx.x;
    __shared__ float avg[256], mxv[256];
    __shared__ float h1[32], hpart[32][8], hcell[16][16], hbar[16];

    avg[tid] = g_gsum[b * NC + tid] * (1.f / (float)NHW);
    mxv[tid] = g_gmax[b * NC + tid];
    __syncthreads();

    {   // h1: 8 partial threads per hidden unit (32 units: 16 avg + 16 max)
        const int m = tid >> 3, part = tid & 7;
        const int mm = m & 15;
        const float* src = (m < 16) ? avg : mxv;
        float a = 0.f;
        #pragma unroll 8
        for (int c = part * 32; c < part * 32 + 32; c++)
            a += mlp_w1[mm * NC + c] * src[c];
        hpart[m][part] = a;
    }
    {   // hcell: one thread per (cell, m)
        const int cell = tid >> 4, m2 = tid & 15;
        float a = 0.f;
        #pragma unroll 8
        for (int c = 0; c < NC; c++)
            a += loc_w1[m2 * NC + c] * g_lsum[(b * NC + c) * 16 + cell];
        hcell[cell][m2] = fmaxf(a * (1.f / 1600.f), 0.f);
    }
    __syncthreads();
    if (tid < 32) {
        float a = 0.f;
        #pragma unroll
        for (int p = 0; p < 8; p++) a += hpart[tid][p];
        h1[tid] = fmaxf(a, 0.f);
    }
    if (tid >= 32 && tid < 48) {
        float s = 0.f;
        #pragma unroll
        for (int cell = 0; cell < 16; cell++) s += hcell[cell][tid - 32];
        hbar[tid - 32] = s * (1.f / 16.f);
    }
    __syncthreads();

    float ga = 0.f, la = 0.f;
    #pragma unroll
    for (int m = 0; m < 16; m++) {
        ga += mlp_w2[tid * 16 + m] * (h1[m] + h1[16 + m]);
        la += loc_w2[tid * 16 + m] * hbar[m];
    }
    const float alpha = sigmoidf_(fusion_w[0]);
    g_ca[b * NC + tid] = sigmoidf_(alpha * ga + (1.f - alpha) * la);
}

// ---------------------------------------------------------------------------
// Kernel 5: sf = [mean_c(ca*x), max_c(ca*x)]  (float4)
// ---------------------------------------------------------------------------
__global__ __launch_bounds__(256) void sf_kernel() {
    const int b = blockIdx.y;
    const int p4 = blockIdx.x * 256 + threadIdx.x;      // 0..6399
    const float4* xb = (const float4*)(g_xal + (size_t)b * NC * NHW);
    const float* cab = g_ca + b * NC;
    float4 s = make_float4(0.f, 0.f, 0.f, 0.f);
    float4 mx = make_float4(-1e30f, -1e30f, -1e30f, -1e30f);
    #pragma unroll 4
    for (int c = 0; c < NC; c++) {
        const float cc = cab[c];
        float4 v = xb[(size_t)c * (NHW / 4) + p4];
        v.x *= cc; v.y *= cc; v.z *= cc; v.w *= cc;
        s.x += v.x; s.y += v.y; s.z += v.z; s.w += v.w;
        mx.x = fmaxf(mx.x, v.x); mx.y = fmaxf(mx.y, v.y);
        mx.z = fmaxf(mx.z, v.z); mx.w = fmaxf(mx.w, v.w);
    }
    const float inv = 1.f / (float)NC;
    s.x *= inv; s.y *= inv; s.z *= inv; s.w *= inv;
    ((float4*)(g_sf + (size_t)b * 2 * NHW))[p4] = s;
    ((float4*)(g_sf + (size_t)b * 2 * NHW + NHW))[p4] = mx;
}

// ---------------------------------------------------------------------------
// Kernel 6: offset conv1: 3x3, 2->16 + BN + ReLU
// ---------------------------------------------------------------------------
__global__ __launch_bounds__(256) void off1_kernel(
    const float* __restrict__ w1, const float* __restrict__ gg,
    const float* __restrict__ bt, const float* __restrict__ mm,
    const float* __restrict__ vv)
{
    const int p = blockIdx.x * blockDim.x + threadIdx.x;
    const int co = blockIdx.y, b = blockIdx.z;
    const int h = p / NW, w = p % NW;
    const float* sfb = g_sf + (size_t)b * 2 * NHW;
    float acc = 0.f;
    #pragma unroll
    for (int ci = 0; ci < 2; ci++) {
        #pragma unroll
        for (int ky = 0; ky < 3; ky++) {
            const int hy = h + ky - 1;
            if (hy < 0 || hy >= NH) continue;
            #pragma unroll
            for (int kx = 0; kx < 3; kx++) {
                const int wx = w + kx - 1;
                if (wx < 0 || wx >= NW) continue;
                acc += w1[((co * 2 + ci) * 3 + ky) * 3 + kx] *
                       sfb[ci * NHW + hy * NW + wx];
            }
        }
    }
    const float sc = gg[co] * rsqrtf(vv[co] + BN_EPS);
    const float tb = bt[co] - mm[co] * sc;
    g_o1[((size_t)b * 16 + co) * NHW + p] = fmaxf(acc * sc + tb, 0.f);
}

// ---------------------------------------------------------------------------
// Kernel 7: averaged offset conv2 + tanh*0.5 + grid + bilinear sample
// ---------------------------------------------------------------------------
__global__ __launch_bounds__(256) void off2_sample_kernel() {
    const int b = blockIdx.y;
    const int p = blockIdx.x * blockDim.x + threadIdx.x;
    const int h = p / NW, w = p % NW;
    const float* o1b = g_o1 + (size_t)b * 16 * NHW;

    float off[2];
    #pragma unroll
    for (int d = 0; d < 2; d++) {
        float acc = g_bavg[d];
        for (int ci = 0; ci < 16; ci++) {
            #pragma unroll
            for (int ky = 0; ky < 3; ky++) {
                const int hy = h + ky - 1;
                if (hy < 0 || hy >= NH) continue;
                #pragma unroll
                for (int kx = 0; kx < 3; kx++) {
                    const int wx = w + kx - 1;
                    if (wx < 0 || wx >= NW) continue;
                    acc += g_wavg[(d * 16 + ci) * 9 + ky * 3 + kx] *
                           o1b[(size_t)ci * NHW + hy * NW + wx];
                }
            }
        }
        off[d] = tanhf(acc) * 0.5f;
    }

    const float bx = -1.f + 2.f * (float)w / 159.f;
    const float by = -1.f + 2.f * (float)h / 159.f;
    const float gx = fminf(fmaxf(bx + off[0], -1.f), 1.f);
    const float gy = fminf(fmaxf(by + off[1], -1.f), 1.f);

    const float fx = (gx + 1.f) * ((float)NW * 0.5f) - 0.5f;
    const float fy = (gy + 1.f) * ((float)NH * 0.5f) - 0.5f;
    const float x0f = floorf(fx), y0f = floorf(fy);
    const int x0 = (int)x0f, y0 = (int)y0f;
    const float wx = fx - x0f, wy = fy - y0f;

    const float* sfb = g_sf + (size_t)b * 2 * NHW;
    float out0 = 0.f, out1 = 0.f;
    #pragma unroll
    for (int dy = 0; dy < 2; dy++) {
        const int yy = y0 + dy;
        if (yy < 0 || yy >= NH) continue;
        const float wgy = dy ? wy : (1.f - wy);
        #pragma unroll
        for (int dx = 0; dx < 2; dx++) {
            const int xx = x0 + dx;
            if (xx < 0 || xx >= NW) continue;
            const float wt = wgy * (dx ? wx : (1.f - wx));
            out0 += wt * sfb[yy * NW + xx];
            out1 += wt * sfb[NHW + yy * NW + xx];
        }
    }
    g_sampled[(size_t)b * 2 * NHW + p] = out0;
    g_sampled[(size_t)b * 2 * NHW + NHW + p] = out1;
}

// ---------------------------------------------------------------------------
// Kernel 8: 7x7 conv (2->1) over sampled + sigmoid -> g_sa
// ---------------------------------------------------------------------------
__global__ __launch_bounds__(256) void sa_kernel(const float* __restrict__ attn_w) {
    const int b = blockIdx.y;
    const int p = blockIdx.x * blockDim.x + threadIdx.x;
    const int h = p / NW, w = p % NW;
    const float* sm = g_sampled + (size_t)b * 2 * NHW;
    float acc = 0.f;
    #pragma unroll
    for (int ci = 0; ci < 2; ci++) {
        #pragma unroll
        for (int ky = 0; ky < 7; ky++) {
            const int hy = h + ky - 3;
            if (hy < 0 || hy >= NH) continue;
            #pragma unroll
            for (int kx = 0; kx < 7; kx++) {
                const int wx = w + kx - 3;
                if (wx < 0 || wx >= NW) continue;
                acc += attn_w[(ci * 7 + ky) * 7 + kx] *
                       sm[ci * NHW + hy * NW + wx];
            }
        }
    }
    g_sa[b * NHW + p] = sigmoidf_(acc);
}

// ---------------------------------------------------------------------------
// Kernel 9: out = sa * ca * x_aligned
// ---------------------------------------------------------------------------
__global__ __launch_bounds__(256) void final_kernel(float* __restrict__ out) {
    const unsigned idx4 = blockIdx.x * blockDim.x + threadIdx.x;
    const unsigned total4 = (unsigned)NB * NC * NHW / 4;
    if (idx4 >= total4) return;
    const unsigned e = idx4 * 4;
    const unsigned p = e % NHW;
    const unsigned c = (e / NHW) % NC;
    const unsigned b = e / (NHW * NC);
    const float4 xv = *reinterpret_cast<const float4*>(&g_xal[e]);
    const float4 sav = *reinterpret_cast<const float4*>(&g_sa[b * NHW + p]);
    const float cc = g_ca[b * NC + c];
    float4 r;
    r.x = xv.x * sav.x * cc;
    r.y = xv.y * sav.y * cc;
    r.z = xv.z * sav.z * cc;
    r.w = xv.w * sav.w * cc;
    *reinterpret_cast<float4*>(&out[e]) = r;
}

// ---------------------------------------------------------------------------
extern "C" void kernel_launch(void* const* d_in, const int* in_sizes, int n_in,
                              void* d_out, int out_size) {
    const float* x       = (const float*)d_in[0];
    const float* align_w = (const float*)d_in[1];
    const float* align_g = (const float*)d_in[2];
    const float* align_b = (const float*)d_in[3];
    const float* align_m = (const float*)d_in[4];
    const float* align_v = (const float*)d_in[5];
    const float* mlp_w1  = (const float*)d_in[6];
    const float* mlp_w2  = (const float*)d_in[7];
    const float* loc_w1  = (const float*)d_in[8];
    const float* loc_w2  = (const float*)d_in[9];
    const float* fusion  = (const float*)d_in[10];
    const float* off_w1  = (const float*)d_in[11];
    const float* off_g   = (const float*)d_in[12];
    const float* off_bt  = (const float*)d_in[13];
    const float* off_m   = (const float*)d_in[14];
    const float* off_v   = (const float*)d_in[15];
    const float* off_w2  = (const float*)d_in[16];
    const float* off_b2  = (const float*)d_in[17];
    const float* attn_w  = (const float*)d_in[18];
    float* out = (float*)d_out;

    wpack_kernel<<<128, 256>>>(align_w, align_g, align_b, align_m, align_v);
    prep_kernel<<<1, 288>>>(off_w2, off_b2);

    dim3 gGemm(NHW / 128, 2, NB);
    gemm_kernel<<<gGemm, 256>>>(x);

    pool_kernel<<<NB * NC, 160>>>();
    ca_kernel<<<NB, 256>>>(mlp_w1, mlp_w2, loc_w1, loc_w2, fusion);

    dim3 gPix4(NHW / 4 / 256, NB);
    sf_kernel<<<gPix4, 256>>>();

    dim3 gPix(NHW / 256, NB);
    dim3 gOff1(NHW / 256, 16, NB);
    off1_kernel<<<gOff1, 256>>>(off_w1, off_g, off_bt, off_m, off_v);
    off2_sample_kernel<<<gPix, 256>>>();
    sa_kernel<<<gPix, 256>>>(attn_w);

    const unsigned total4 = (unsigned)NB * NC * NHW / 4;
    final_kernel<<<(total4 + 255) / 256, 256>>>(out);
}

// round 4
// speedup vs baseline: 1.5386x; 1.1298x over previous
#include <cuda_runtime.h>
#include <cuda_bf16.h>
#include <cstdint>

static constexpr int NB = 8;
static constexpr int NC = 256;
static constexpr int NH = 160;
static constexpr int NW = 160;
static constexpr int NHW = NH * NW;           // 25600
static constexpr int NTILES = NHW / 128;      // 200
static constexpr float BN_EPS = 1e-5f;

// ---------------- scratch (static device globals) --------------------------
__device__ float g_xal[(size_t)NB * NC * NHW];
__device__ uint32_t g_wph[NC * 128];     // packed bf16x2 (k-pairs) scaled W, hi
__device__ uint32_t g_wpl[NC * 128];     // lo residual
__device__ float g_bias[NC];
__device__ float g_gsum[NB * NC];
__device__ float g_gmax[NB * NC];
__device__ float g_lsum[NB * NC * 16];
__device__ float g_ca[NB * NC];
__device__ float g_sf[NB * 2 * NHW];
__device__ float g_o1[NB * 16 * NHW];
__device__ float g_sampled[NB * 2 * NHW];
__device__ float g_sa[NB * NHW];
__device__ float g_wavg[2 * 16 * 9];
__device__ float g_bavg[2];

__device__ __forceinline__ float sigmoidf_(float x) {
    return 1.f / (1.f + __expf(-x));
}
__device__ __forceinline__ uint32_t packbf(float a, float b) {
    __nv_bfloat162 t = __floats2bfloat162_rn(a, b);   // low = a
    return *reinterpret_cast<uint32_t*>(&t);
}
__device__ __forceinline__ void mma16816(float* c, const uint32_t* a,
                                         uint32_t b0, uint32_t b1) {
    asm volatile(
        "mma.sync.aligned.m16n8k16.row.col.f32.bf16.bf16.f32 "
        "{%0,%1,%2,%3}, {%4,%5,%6,%7}, {%8,%9}, {%0,%1,%2,%3};"
        : "+f"(c[0]), "+f"(c[1]), "+f"(c[2]), "+f"(c[3])
        : "r"(a[0]), "r"(a[1]), "r"(a[2]), "r"(a[3]), "r"(b0), "r"(b1));
}
__device__ __forceinline__ void ldsm4(uint32_t* d, uint32_t addr) {
    asm volatile(
        "ldmatrix.sync.aligned.m8n8.x4.shared.b16 {%0,%1,%2,%3}, [%4];"
        : "=r"(d[0]), "=r"(d[1]), "=r"(d[2]), "=r"(d[3]) : "r"(addr));
}

// ---------------------------------------------------------------------------
// Kernel 0: pack BN-scaled weights into split-bf16 k-pairs
// ---------------------------------------------------------------------------
__global__ __launch_bounds__(256) void wpack_kernel(
    const float* __restrict__ w, const float* __restrict__ g,
    const float* __restrict__ bb, const float* __restrict__ m,
    const float* __restrict__ v)
{
    const int id = blockIdx.x * 256 + threadIdx.x;   // 0..32767
    const int co = id >> 7, kp = id & 127;
    const float sc = g[co] * rsqrtf(v[co] + BN_EPS);
    const float w0 = w[co * 256 + 2 * kp] * sc;
    const float w1 = w[co * 256 + 2 * kp + 1] * sc;
    const float h0 = __bfloat162float(__float2bfloat16(w0));
    const float h1 = __bfloat162float(__float2bfloat16(w1));
    g_wph[co * 128 + kp] = packbf(h0, h1);
    g_wpl[co * 128 + kp] = packbf(w0 - h0, w1 - h1);
    if (kp == 0) g_bias[co] = bb[co] - m[co] * sc;
}

// ---------------------------------------------------------------------------
// Kernel 1: tensor-core GEMM, CTA = [256 co x 128 px], K=256, split bf16.
//   - W double-buffered via cp.async (pre-packed, no conversion)
//   - X register-prefetched, converted in regs, single smem stage
//   - ldmatrix fragment loads (stride-20 rows: conflict-free)
// Dynamic smem: W 2 stages (h+l) + X (h+l) = 25600 u32 = 100KB
// ---------------------------------------------------------------------------
__global__ void __launch_bounds__(256, 1) gemm_kernel(const float* __restrict__ X)
{
    extern __shared__ uint32_t sm[];
    // layout (u32 units): Wh0[5120] Wl0[5120] Wh1[5120] Wl1[5120] Xh[2560] Xl[2560]
    const int tile = blockIdx.x, b = blockIdx.y;
    const int tileBase = tile * 128;
    const int t = threadIdx.x, lane = t & 31, warp = t >> 5;
    const int warpM = warp >> 1, warpN = warp & 1;
    const int q = lane >> 2, r = lane & 3;
    const float* Xb = X + (size_t)b * NC * NHW + tileBase;
    const int kp = t & 15, pg = t >> 4;

    const uint32_t smBase = (uint32_t)__cvta_generic_to_shared(sm);
    const uint32_t xhB = smBase + 20480u * 4u;
    const uint32_t xlB = smBase + 23040u * 4u;
    // ldmatrix per-lane offsets (u32 units)
    const uint32_t aOff = (uint32_t)((warpM * 64 + (lane & 15)) * 20 + ((lane >> 4) << 2));
    const uint32_t bOff = (uint32_t)((warpN * 64 + ((lane & 16) ? 8 : 0) + (lane & 7)) * 20
                                     + ((lane & 8) ? 4 : 0));

    float acc[4][8][4];
    #pragma unroll
    for (int i = 0; i < 4; i++)
        #pragma unroll
        for (int j = 0; j < 8; j++)
            #pragma unroll
            for (int k = 0; k < 4; k++) acc[i][j][k] = 0.f;

    float4 xr0, xr1, xr2, xr3;

    auto cpW = [&](int c, int s) {
        const uint32_t dWh = smBase + (uint32_t)(s * 10240) * 4u;
        const uint32_t dWl = dWh + 5120u * 4u;
        #pragma unroll
        for (int i = 0; i < 4; i++) {
            const int id = i * 256 + t;
            const int row = id >> 2, grp = id & 3;
            const uint32_t off = (uint32_t)(row * 20 + grp * 4) * 4u;
            const uint32_t* s1 = &g_wph[row * 128 + c * 16 + grp * 4];
            const uint32_t* s2 = &g_wpl[row * 128 + c * 16 + grp * 4];
            asm volatile("cp.async.cg.shared.global [%0], [%1], 16;" :: "r"(dWh + off), "l"(s1));
            asm volatile("cp.async.cg.shared.global [%0], [%1], 16;" :: "r"(dWl + off), "l"(s2));
        }
        asm volatile("cp.async.commit_group;");
    };
    auto ldgX = [&](int c) {
        const float* x0 = Xb + (size_t)(c * 32 + 2 * kp) * NHW + pg * 8;
        const float* x1 = x0 + NHW;
        xr0 = *(const float4*)x0; xr1 = *(const float4*)(x0 + 4);
        xr2 = *(const float4*)x1; xr3 = *(const float4*)(x1 + 4);
    };

    cpW(0, 0);
    ldgX(0);

    for (int c = 0; c < 8; c++) {
        // convert prefetched X to split bf16 pairs
        float e0[8] = {xr0.x, xr0.y, xr0.z, xr0.w, xr1.x, xr1.y, xr1.z, xr1.w};
        float e1[8] = {xr2.x, xr2.y, xr2.z, xr2.w, xr3.x, xr3.y, xr3.z, xr3.w};
        uint32_t hx[8], lx[8];
        #pragma unroll
        for (int j = 0; j < 8; j++) {
            const float h0 = __bfloat162float(__float2bfloat16(e0[j]));
            const float h1 = __bfloat162float(__float2bfloat16(e1[j]));
            hx[j] = packbf(h0, h1);
            lx[j] = packbf(e0[j] - h0, e1[j] - h1);
        }
        __syncthreads();                       // prev compute done with X stage
        #pragma unroll
        for (int j = 0; j < 8; j++) {
            sm[20480 + (pg * 8 + j) * 20 + kp] = hx[j];
            sm[23040 + (pg * 8 + j) * 20 + kp] = lx[j];
        }
        if (c < 7) {
            cpW(c + 1, (c + 1) & 1);
            asm volatile("cp.async.wait_group 1;");   // W(c) landed, W(c+1) in flight
        } else {
            asm volatile("cp.async.wait_group 0;");
        }
        __syncthreads();
        if (c < 7) ldgX(c + 1);                // overlaps compute below

        const uint32_t whB = smBase + (uint32_t)((c & 1) * 10240) * 4u;
        const uint32_t wlB = whB + 5120u * 4u;
        #pragma unroll
        for (int ks = 0; ks < 2; ks++) {
            uint32_t A[4][4];
            #pragma unroll
            for (int mt = 0; mt < 4; mt++)
                ldsm4(A[mt], whB + (aOff + mt * 320 + ks * 8) * 4u);
            #pragma unroll
            for (int np = 0; np < 4; np++) {
                uint32_t B0[4], B1[4];
                ldsm4(B0, xhB + (bOff + np * 320 + ks * 8) * 4u);
                ldsm4(B1, xlB + (bOff + np * 320 + ks * 8) * 4u);
                #pragma unroll
                for (int j = 0; j < 2; j++)
                    #pragma unroll
                    for (int mt = 0; mt < 4; mt++) {
                        mma16816(acc[mt][np * 2 + j], A[mt], B0[2 * j], B0[2 * j + 1]);
                        mma16816(acc[mt][np * 2 + j], A[mt], B1[2 * j], B1[2 * j + 1]);
                    }
            }
            // pass 2: W-lo x X-hi
            #pragma unroll
            for (int mt = 0; mt < 4; mt++)
                ldsm4(A[mt], wlB + (aOff + mt * 320 + ks * 8) * 4u);
            #pragma unroll
            for (int np = 0; np < 4; np++) {
                uint32_t B0[4];
                ldsm4(B0, xhB + (bOff + np * 320 + ks * 8) * 4u);
                #pragma unroll
                for (int j = 0; j < 2; j++)
                    #pragma unroll
                    for (int mt = 0; mt < 4; mt++)
                        mma16816(acc[mt][np * 2 + j], A[mt], B0[2 * j], B0[2 * j + 1]);
            }
        }
    }

    // ---- epilogue: bias + SiLU + store ----
    #pragma unroll
    for (int mt = 0; mt < 4; mt++) {
        const int co0 = warpM * 64 + mt * 16 + q;
        const int co1 = co0 + 8;
        const float tb0 = g_bias[co0], tb1 = g_bias[co1];
        float* y0 = g_xal + ((size_t)b * NC + co0) * NHW + tileBase;
        float* y1 = g_xal + ((size_t)b * NC + co1) * NHW + tileBase;
        #pragma unroll
        for (int nt = 0; nt < 8; nt++) {
            const int pix = warpN * 64 + nt * 8 + 2 * r;
            float v0 = acc[mt][nt][0] + tb0, v1 = acc[mt][nt][1] + tb0;
            float v2 = acc[mt][nt][2] + tb1, v3 = acc[mt][nt][3] + tb1;
            *(float2*)&y0[pix] = make_float2(v0 * sigmoidf_(v0), v1 * sigmoidf_(v1));
            *(float2*)&y1[pix] = make_float2(v2 * sigmoidf_(v2), v3 * sigmoidf_(v3));
        }
    }
}

// ---------------------------------------------------------------------------
// Kernel 2: per-(b,c) global sum/max + 4x4 local pool sums (static bins)
// 160 threads: wb = t&3 (cell col), hr = t>>2 (row within 40-row band)
// ---------------------------------------------------------------------------
__global__ __launch_bounds__(160) void pool_kernel() {
    const int bc = blockIdx.x;
    const float4* plane = (const float4*)(g_xal + (size_t)bc * NHW);
    const int t = threadIdx.x, wb = t & 3, hr = t >> 2;

    float cell[4];
    float gmx = -1e30f;
    #pragma unroll
    for (int gy = 0; gy < 4; gy++) {
        const float4* rp = plane + ((gy * 40 + hr) * NW + wb * 40) / 4;
        float s = 0.f;
        #pragma unroll
        for (int i = 0; i < 10; i++) {
            float4 v = rp[i];
            s += (v.x + v.y) + (v.z + v.w);
            gmx = fmaxf(gmx, fmaxf(fmaxf(v.x, v.y), fmaxf(v.z, v.w)));
        }
        cell[gy] = s;
    }
    float gs = (cell[0] + cell[1]) + (cell[2] + cell[3]);

    #pragma unroll
    for (int o = 4; o <= 16; o <<= 1)
        #pragma unroll
        for (int gy = 0; gy < 4; gy++)
            cell[gy] += __shfl_xor_sync(0xffffffffu, cell[gy], o);
    #pragma unroll
    for (int o = 1; o <= 16; o <<= 1) {
        gs += __shfl_xor_sync(0xffffffffu, gs, o);
        gmx = fmaxf(gmx, __shfl_xor_sync(0xffffffffu, gmx, o));
    }

    __shared__ float sC[5][4][4], sS[5], sM[5];
    const int w = t >> 5, lanei = t & 31;
    if (lanei < 4) {
        #pragma unroll
        for (int gy = 0; gy < 4; gy++) sC[w][gy][lanei] = cell[gy];
    }
    if (lanei == 0) { sS[w] = gs; sM[w] = gmx; }
    __syncthreads();
    if (t < 16) {
        float v = 0.f;
        #pragma unroll
        for (int w2 = 0; w2 < 5; w2++) v += sC[w2][t >> 2][t & 3];
        g_lsum[bc * 16 + t] = v;
    }
    if (t == 0) {
        float S = 0.f, M = -1e30f;
        #pragma unroll
        for (int w2 = 0; w2 < 5; w2++) { S += sS[w2]; M = fmaxf(M, sM[w2]); }
        g_gsum[bc] = S;
        g_gmax[bc] = M;
    }
}

// ---------------------------------------------------------------------------
// Kernel 3: pre-average offset conv2 weights over the 49 output taps
// ---------------------------------------------------------------------------
__global__ void prep_kernel(const float* __restrict__ off_w2,
                            const float* __restrict__ off_b2) {
    const int i = threadIdx.x;
    if (i < 288) {
        const int d = i / 144, rest = i % 144;
        float s = 0.f;
        for (int j = 0; j < 49; j++) s += off_w2[(d * 49 + j) * 144 + rest];
        g_wavg[i] = s * (1.f / 49.f);
    }
    if (i < 2) {
        float s = 0.f;
        for (int j = 0; j < 49; j++) s += off_b2[i * 49 + j];
        g_bavg[i] = s * (1.f / 49.f);
    }
}

// ---------------------------------------------------------------------------
// Kernel 4: channel attention -> g_ca
// ---------------------------------------------------------------------------
__global__ __launch_bounds__(256) void ca_kernel(
    const float* __restrict__ mlp_w1, const float* __restrict__ mlp_w2,
    const float* __restrict__ loc_w1, const float* __restrict__ loc_w2,
    const float* __restrict__ fusion_w)
{
    const int b = blockIdx.x, tid = threadIdx.x;
    __shared__ float avg[256], mxv[256];
    __shared__ float h1[32], hpart[32][8], hcell[16][16], hbar[16];

    avg[tid] = g_gsum[b * NC + tid] * (1.f / (float)NHW);
    mxv[tid] = g_gmax[b * NC + tid];
    __syncthreads();

    {
        const int m = tid >> 3, part = tid & 7;
        const int mm = m & 15;
        const float* src = (m < 16) ? avg : mxv;
        float a = 0.f;
        #pragma unroll 8
        for (int c = part * 32; c < part * 32 + 32; c++)
            a += mlp_w1[mm * NC + c] * src[c];
        hpart[m][part] = a;
    }
    {
        const int cell = tid >> 4, m2 = tid & 15;
        float a = 0.f;
        #pragma unroll 8
        for (int c = 0; c < NC; c++)
            a += loc_w1[m2 * NC + c] * g_lsum[(b * NC + c) * 16 + cell];
        hcell[cell][m2] = fmaxf(a * (1.f / 1600.f), 0.f);
    }
    __syncthreads();
    if (tid < 32) {
        float a = 0.f;
        #pragma unroll
        for (int p = 0; p < 8; p++) a += hpart[tid][p];
        h1[tid] = fmaxf(a, 0.f);
    }
    if (tid >= 32 && tid < 48) {
        float s = 0.f;
        #pragma unroll
        for (int cell = 0; cell < 16; cell++) s += hcell[cell][tid - 32];
        hbar[tid - 32] = s * (1.f / 16.f);
    }
    __syncthreads();

    float ga = 0.f, la = 0.f;
    #pragma unroll
    for (int m = 0; m < 16; m++) {
        ga += mlp_w2[tid * 16 + m] * (h1[m] + h1[16 + m]);
        la += loc_w2[tid * 16 + m] * hbar[m];
    }
    const float alpha = sigmoidf_(fusion_w[0]);
    g_ca[b * NC + tid] = sigmoidf_(alpha * ga + (1.f - alpha) * la);
}

// ---------------------------------------------------------------------------
// Kernel 5: sf = [mean_c(ca*x), max_c(ca*x)]  (float4)
// ---------------------------------------------------------------------------
__global__ __launch_bounds__(256) void sf_kernel() {
    const int b = blockIdx.y;
    const int p4 = blockIdx.x * 256 + threadIdx.x;      // 0..6399
    const float4* xb = (const float4*)(g_xal + (size_t)b * NC * NHW);
    const float* cab = g_ca + b * NC;
    float4 s = make_float4(0.f, 0.f, 0.f, 0.f);
    float4 mx = make_float4(-1e30f, -1e30f, -1e30f, -1e30f);
    #pragma unroll 4
    for (int c = 0; c < NC; c++) {
        const float cc = cab[c];
        float4 v = xb[(size_t)c * (NHW / 4) + p4];
        v.x *= cc; v.y *= cc; v.z *= cc; v.w *= cc;
        s.x += v.x; s.y += v.y; s.z += v.z; s.w += v.w;
        mx.x = fmaxf(mx.x, v.x); mx.y = fmaxf(mx.y, v.y);
        mx.z = fmaxf(mx.z, v.z); mx.w = fmaxf(mx.w, v.w);
    }
    const float inv = 1.f / (float)NC;
    s.x *= inv; s.y *= inv; s.z *= inv; s.w *= inv;
    ((float4*)(g_sf + (size_t)b * 2 * NHW))[p4] = s;
    ((float4*)(g_sf + (size_t)b * 2 * NHW + NHW))[p4] = mx;
}

// ---------------------------------------------------------------------------
// Kernel 6: offset conv1: 3x3, 2->16 + BN + ReLU
// ---------------------------------------------------------------------------
__global__ __launch_bounds__(256) void off1_kernel(
    const float* __restrict__ w1, const float* __restrict__ gg,
    const float* __restrict__ bt, const float* __restrict__ mm,
    const float* __restrict__ vv)
{
    const int p = blockIdx.x * blockDim.x + threadIdx.x;
    const int co = blockIdx.y, b = blockIdx.z;
    const int h = p / NW, w = p % NW;
    const float* sfb = g_sf + (size_t)b * 2 * NHW;
    float acc = 0.f;
    #pragma unroll
    for (int ci = 0; ci < 2; ci++) {
        #pragma unroll
        for (int ky = 0; ky < 3; ky++) {
            const int hy = h + ky - 1;
            if (hy < 0 || hy >= NH) continue;
            #pragma unroll
            for (int kx = 0; kx < 3; kx++) {
                const int wx = w + kx - 1;
                if (wx < 0 || wx >= NW) continue;
                acc += w1[((co * 2 + ci) * 3 + ky) * 3 + kx] *
                       sfb[ci * NHW + hy * NW + wx];
            }
        }
    }
    const float sc = gg[co] * rsqrtf(vv[co] + BN_EPS);
    const float tb = bt[co] - mm[co] * sc;
    g_o1[((size_t)b * 16 + co) * NHW + p] = fmaxf(acc * sc + tb, 0.f);
}

// ---------------------------------------------------------------------------
// Kernel 7: averaged offset conv2 + tanh*0.5 + grid + bilinear sample
// ---------------------------------------------------------------------------
__global__ __launch_bounds__(256) void off2_sample_kernel() {
    const int b = blockIdx.y;
    const int p = blockIdx.x * blockDim.x + threadIdx.x;
    const int h = p / NW, w = p % NW;
    const float* o1b = g_o1 + (size_t)b * 16 * NHW;

    float off[2];
    #pragma unroll
    for (int d = 0; d < 2; d++) {
        float acc = g_bavg[d];
        for (int ci = 0; ci < 16; ci++) {
            #pragma unroll
            for (int ky = 0; ky < 3; ky++) {
                const int hy = h + ky - 1;
                if (hy < 0 || hy >= NH) continue;
                #pragma unroll
                for (int kx = 0; kx < 3; kx++) {
                    const int wx = w + kx - 1;
                    if (wx < 0 || wx >= NW) continue;
                    acc += g_wavg[(d * 16 + ci) * 9 + ky * 3 + kx] *
                           o1b[(size_t)ci * NHW + hy * NW + wx];
                }
            }
        }
        off[d] = tanhf(acc) * 0.5f;
    }

    const float bx = -1.f + 2.f * (float)w / 159.f;
    const float by = -1.f + 2.f * (float)h / 159.f;
    const float gx = fminf(fmaxf(bx + off[0], -1.f), 1.f);
    const float gy = fminf(fmaxf(by + off[1], -1.f), 1.f);

    const float fx = (gx + 1.f) * ((float)NW * 0.5f) - 0.5f;
    const float fy = (gy + 1.f) * ((float)NH * 0.5f) - 0.5f;
    const float x0f = floorf(fx), y0f = floorf(fy);
    const int x0 = (int)x0f, y0 = (int)y0f;
    const float wx = fx - x0f, wy = fy - y0f;

    const float* sfb = g_sf + (size_t)b * 2 * NHW;
    float out0 = 0.f, out1 = 0.f;
    #pragma unroll
    for (int dy = 0; dy < 2; dy++) {
        const int yy = y0 + dy;
        if (yy < 0 || yy >= NH) continue;
        const float wgy = dy ? wy : (1.f - wy);
        #pragma unroll
        for (int dx = 0; dx < 2; dx++) {
            const int xx = x0 + dx;
            if (xx < 0 || xx >= NW) continue;
            const float wt = wgy * (dx ? wx : (1.f - wx));
            out0 += wt * sfb[yy * NW + xx];
            out1 += wt * sfb[NHW + yy * NW + xx];
        }
    }
    g_sampled[(size_t)b * 2 * NHW + p] = out0;
    g_sampled[(size_t)b * 2 * NHW + NHW + p] = out1;
}

// ---------------------------------------------------------------------------
// Kernel 8: 7x7 conv (2->1) over sampled + sigmoid -> g_sa
// ---------------------------------------------------------------------------
__global__ __launch_bounds__(256) void sa_kernel(const float* __restrict__ attn_w) {
    const int b = blockIdx.y;
    const int p = blockIdx.x * blockDim.x + threadIdx.x;
    const int h = p / NW, w = p % NW;
    const float* sm = g_sampled + (size_t)b * 2 * NHW;
    float acc = 0.f;
    #pragma unroll
    for (int ci = 0; ci < 2; ci++) {
        #pragma unroll
        for (int ky = 0; ky < 7; ky++) {
            const int hy = h + ky - 3;
            if (hy < 0 || hy >= NH) continue;
            #pragma unroll
            for (int kx = 0; kx < 7; kx++) {
                const int wx = w + kx - 3;
                if (wx < 0 || wx >= NW) continue;
                acc += attn_w[(ci * 7 + ky) * 7 + kx] *
                       sm[ci * NHW + hy * NW + wx];
            }
        }
    }
    g_sa[b * NHW + p] = sigmoidf_(acc);
}

// ---------------------------------------------------------------------------
// Kernel 9: out = sa * ca * x_aligned
// ---------------------------------------------------------------------------
__global__ __launch_bounds__(256) void final_kernel(float* __restrict__ out) {
    const unsigned idx4 = blockIdx.x * blockDim.x + threadIdx.x;
    const unsigned total4 = (unsigned)NB * NC * NHW / 4;
    if (idx4 >= total4) return;
    const unsigned e = idx4 * 4;
    const unsigned p = e % NHW;
    const unsigned c = (e / NHW) % NC;
    const unsigned b = e / (NHW * NC);
    const float4 xv = *reinterpret_cast<const float4*>(&g_xal[e]);
    const float4 sav = *reinterpret_cast<const float4*>(&g_sa[b * NHW + p]);
    const float cc = g_ca[b * NC + c];
    float4 r;
    r.x = xv.x * sav.x * cc;
    r.y = xv.y * sav.y * cc;
    r.z = xv.z * sav.z * cc;
    r.w = xv.w * sav.w * cc;
    *reinterpret_cast<float4*>(&out[e]) = r;
}

// ---------------------------------------------------------------------------
extern "C" void kernel_launch(void* const* d_in, const int* in_sizes, int n_in,
                              void* d_out, int out_size) {
    const float* x       = (const float*)d_in[0];
    const float* align_w = (const float*)d_in[1];
    const float* align_g = (const float*)d_in[2];
    const float* align_b = (const float*)d_in[3];
    const float* align_m = (const float*)d_in[4];
    const float* align_v = (const float*)d_in[5];
    const float* mlp_w1  = (const float*)d_in[6];
    const float* mlp_w2  = (const float*)d_in[7];
    const float* loc_w1  = (const float*)d_in[8];
    const float* loc_w2  = (const float*)d_in[9];
    const float* fusion  = (const float*)d_in[10];
    const float* off_w1  = (const float*)d_in[11];
    const float* off_g   = (const float*)d_in[12];
    const float* off_bt  = (const float*)d_in[13];
    const float* off_m   = (const float*)d_in[14];
    const float* off_v   = (const float*)d_in[15];
    const float* off_w2  = (const float*)d_in[16];
    const float* off_b2  = (const float*)d_in[17];
    const float* attn_w  = (const float*)d_in[18];
    float* out = (float*)d_out;

    static bool attrSet = false;
    if (!attrSet) {
        cudaFuncSetAttribute(gemm_kernel,
                             cudaFuncAttributeMaxDynamicSharedMemorySize, 102400);
        attrSet = true;
    }

    wpack_kernel<<<128, 256>>>(align_w, align_g, align_b, align_m, align_v);
    prep_kernel<<<1, 288>>>(off_w2, off_b2);

    dim3 gGemm(NTILES, NB);
    gemm_kernel<<<gGemm, 256, 102400>>>(x);

    pool_kernel<<<NB * NC, 160>>>();
    ca_kernel<<<NB, 256>>>(mlp_w1, mlp_w2, loc_w1, loc_w2, fusion);

    dim3 gPix4(NHW / 4 / 256, NB);
    sf_kernel<<<gPix4, 256>>>();

    dim3 gPix(NHW / 256, NB);
    dim3 gOff1(NHW / 256, 16, NB);
    off1_kernel<<<gOff1, 256>>>(off_w1, off_g, off_bt, off_m, off_v);
    off2_sample_kernel<<<gPix, 256>>>();
    sa_kernel<<<gPix, 256>>>(attn_w);

    const unsigned total4 = (unsigned)NB * NC * NHW / 4;
    final_kernel<<<(total4 + 255) / 256, 256>>>(out);
}

// round 7
// speedup vs baseline: 1.6203x; 1.0531x over previous
#include <cuda_runtime.h>
#include <cuda_bf16.h>
#include <cstdint>

static constexpr int NB = 8;
static constexpr int NC = 256;
static constexpr int NH = 160;
static constexpr int NW = 160;
static constexpr int NHW = NH * NW;           // 25600
static constexpr int TILE_N = 64;
static constexpr int NTILES = NHW / TILE_N;   // 400
static constexpr float BN_EPS = 1e-5f;

// dynamic smem layout (u32 units):
//   Wh0[5120] Wl0[5120] Wh1[5120] Wl1[5120] Xh[1280] Xl[1280]  = 23040 u32 = 90KB
static constexpr int SM_XH = 20480;
static constexpr int SM_XL = 21760;
static constexpr int DSMEM_U32 = 23040;

// ---------------- scratch (static device globals) --------------------------
__device__ float g_xal[(size_t)NB * NC * NHW];
__device__ uint32_t g_wph[NC * 128];     // packed bf16x2 (k-pairs) scaled W, hi
__device__ uint32_t g_wpl[NC * 128];     // lo residual
__device__ float g_bias[NC];
__device__ float g_gsum[NB * NC];
__device__ float g_gmax[NB * NC];
__device__ float g_lsum[NB * NC * 16];
__device__ float g_ca[NB * NC];
__device__ float g_sf[NB * 2 * NHW];
__device__ float g_o1[NB * 16 * NHW];
__device__ float g_sampled[NB * 2 * NHW];
__device__ float g_sa[NB * NHW];
__device__ float g_wavg[2 * 16 * 9];
__device__ float g_bavg[2];

__device__ __forceinline__ float sigmoidf_(float x) {
    return 1.f / (1.f + __expf(-x));
}
__device__ __forceinline__ uint32_t packbf(float a, float b) {
    __nv_bfloat162 t = __floats2bfloat162_rn(a, b);   // low = a
    return *reinterpret_cast<uint32_t*>(&t);
}
__device__ __forceinline__ void mma16816(float* c, const uint32_t* a,
                                         uint32_t b0, uint32_t b1) {
    asm volatile(
        "mma.sync.aligned.m16n8k16.row.col.f32.bf16.bf16.f32 "
        "{%0,%1,%2,%3}, {%4,%5,%6,%7}, {%8,%9}, {%0,%1,%2,%3};"
        : "+f"(c[0]), "+f"(c[1]), "+f"(c[2]), "+f"(c[3])
        : "r"(a[0]), "r"(a[1]), "r"(a[2]), "r"(a[3]), "r"(b0), "r"(b1));
}
__device__ __forceinline__ void ldsm4(uint32_t* d, uint32_t addr) {
    asm volatile(
        "ldmatrix.sync.aligned.m8n8.x4.shared.b16 {%0,%1,%2,%3}, [%4];"
        : "=r"(d[0]), "=r"(d[1]), "=r"(d[2]), "=r"(d[3]) : "r"(addr));
}

// ---------------------------------------------------------------------------
// Kernel 0: pack BN-scaled weights into split-bf16 k-pairs
// ---------------------------------------------------------------------------
__global__ __launch_bounds__(256) void wpack_kernel(
    const float* __restrict__ w, const float* __restrict__ g,
    const float* __restrict__ bb, const float* __restrict__ m,
    const float* __restrict__ v)
{
    const int id = blockIdx.x * 256 + threadIdx.x;   // 0..32767
    const int co = id >> 7, kp = id & 127;
    const float sc = g[co] * rsqrtf(v[co] + BN_EPS);
    const float w0 = w[co * 256 + 2 * kp] * sc;
    const float w1 = w[co * 256 + 2 * kp + 1] * sc;
    const float h0 = __bfloat162float(__float2bfloat16(w0));
    const float h1 = __bfloat162float(__float2bfloat16(w1));
    g_wph[co * 128 + kp] = packbf(h0, h1);
    g_wpl[co * 128 + kp] = packbf(w0 - h0, w1 - h1);
    if (kp == 0) g_bias[co] = bb[co] - m[co] * sc;
}

// ---------------------------------------------------------------------------
// Kernel 1: tensor-core GEMM, CTA = [256 co x 64 px], K=256, split bf16.
//   - occupancy 2 (64 accum regs/thread, 90KB smem)
//   - W double-buffered cp.async, X register-prefetch + single smem stage
// ---------------------------------------------------------------------------
__global__ void __launch_bounds__(256, 2) gemm_kernel(const float* __restrict__ X)
{
    extern __shared__ uint32_t sm[];
    const int tile = blockIdx.x, b = blockIdx.y;
    const int tileBase = tile * TILE_N;
    const int t = threadIdx.x, lane = t & 31, warp = t >> 5;   // warp = warpM 0..7
    const int q = lane >> 2, r = lane & 3;
    const float* Xb = X + (size_t)b * NC * NHW + tileBase;
    const int kp = t & 15, pg = t >> 4;       // X staging: kpair, pixel group of 4

    const uint32_t smBase = (uint32_t)__cvta_generic_to_shared(sm);
    const uint32_t xhB = smBase + SM_XH * 4u;
    const uint32_t xlB = smBase + SM_XL * 4u;
    // ldmatrix per-lane offsets (u32 units)
    const uint32_t aOff = (uint32_t)((warp * 32 + (lane & 15)) * 20 + ((lane >> 4) << 2));
    const uint32_t bOff = (uint32_t)((((lane & 16) ? 8 : 0) + (lane & 7)) * 20
                                     + ((lane & 8) ? 4 : 0));

    float acc[2][8][4];
    #pragma unroll
    for (int i = 0; i < 2; i++)
        #pragma unroll
        for (int j = 0; j < 8; j++)
            #pragma unroll
            for (int k = 0; k < 4; k++) acc[i][j][k] = 0.f;

    float4 xr0, xr1;

    auto cpW = [&](int c, int s) {
        const uint32_t dWh = smBase + (uint32_t)(s * 10240) * 4u;
        const uint32_t dWl = dWh + 5120u * 4u;
        #pragma unroll
        for (int i = 0; i < 4; i++) {
            const int id = i * 256 + t;
            const int row = id >> 2, grp = id & 3;
            const uint32_t off = (uint32_t)(row * 20 + grp * 4) * 4u;
            const uint32_t* s1 = &g_wph[row * 128 + c * 16 + grp * 4];
            const uint32_t* s2 = &g_wpl[row * 128 + c * 16 + grp * 4];
            asm volatile("cp.async.cg.shared.global [%0], [%1], 16;" :: "r"(dWh + off), "l"(s1));
            asm volatile("cp.async.cg.shared.global [%0], [%1], 16;" :: "r"(dWl + off), "l"(s2));
        }
        asm volatile("cp.async.commit_group;");
    };
    auto ldgX = [&](int c) {
        const float* x0 = Xb + (size_t)(c * 32 + 2 * kp) * NHW + pg * 4;
        xr0 = *(const float4*)x0;
        xr1 = *(const float4*)(x0 + NHW);
    };

    cpW(0, 0);
    ldgX(0);

    for (int c = 0; c < 8; c++) {
        // convert prefetched X to split bf16 pairs
        float e0[4] = {xr0.x, xr0.y, xr0.z, xr0.w};
        float e1[4] = {xr1.x, xr1.y, xr1.z, xr1.w};
        uint32_t hx[4], lx[4];
        #pragma unroll
        for (int j = 0; j < 4; j++) {
            const float h0 = __bfloat162float(__float2bfloat16(e0[j]));
            const float h1 = __bfloat162float(__float2bfloat16(e1[j]));
            hx[j] = packbf(h0, h1);
            lx[j] = packbf(e0[j] - h0, e1[j] - h1);
        }
        __syncthreads();                       // prev compute done with X stage
        #pragma unroll
        for (int j = 0; j < 4; j++) {
            sm[SM_XH + (pg * 4 + j) * 20 + kp] = hx[j];
            sm[SM_XL + (pg * 4 + j) * 20 + kp] = lx[j];
        }
        if (c < 7) {
            cpW(c + 1, (c + 1) & 1);
            asm volatile("cp.async.wait_group 1;");   // W(c) landed, W(c+1) in flight
        } else {
            asm volatile("cp.async.wait_group 0;");
        }
        __syncthreads();
        if (c < 7) ldgX(c + 1);                // overlaps compute below

        const uint32_t whB = smBase + (uint32_t)((c & 1) * 10240) * 4u;
        const uint32_t wlB = whB + 5120u * 4u;
        #pragma unroll
        for (int ks = 0; ks < 2; ks++) {
            uint32_t A[2][4];
            #pragma unroll
            for (int mt = 0; mt < 2; mt++)
                ldsm4(A[mt], whB + (aOff + mt * 320 + ks * 8) * 4u);
            #pragma unroll
            for (int np = 0; np < 4; np++) {
                uint32_t B0[4], B1[4];
                ldsm4(B0, xhB + (bOff + np * 320 + ks * 8) * 4u);
                ldsm4(B1, xlB + (bOff + np * 320 + ks * 8) * 4u);
                #pragma unroll
                for (int j = 0; j < 2; j++)
                    #pragma unroll
                    for (int mt = 0; mt < 2; mt++) {
                        mma16816(acc[mt][np * 2 + j], A[mt], B0[2 * j], B0[2 * j + 1]);
                        mma16816(acc[mt][np * 2 + j], A[mt], B1[2 * j], B1[2 * j + 1]);
                    }
            }
            // pass 2: W-lo x X-hi
            #pragma unroll
            for (int mt = 0; mt < 2; mt++)
                ldsm4(A[mt], wlB + (aOff + mt * 320 + ks * 8) * 4u);
            #pragma unroll
            for (int np = 0; np < 4; np++) {
                uint32_t B0[4];
                ldsm4(B0, xhB + (bOff + np * 320 + ks * 8) * 4u);
                #pragma unroll
                for (int j = 0; j < 2; j++)
                    #pragma unroll
                    for (int mt = 0; mt < 2; mt++)
                        mma16816(acc[mt][np * 2 + j], A[mt], B0[2 * j], B0[2 * j + 1]);
            }
        }
    }

    // ---- epilogue: bias + SiLU + store ----
    #pragma unroll
    for (int mt = 0; mt < 2; mt++) {
        const int co0 = warp * 32 + mt * 16 + q;
        const int co1 = co0 + 8;
        const float tb0 = g_bias[co0], tb1 = g_bias[co1];
        float* y0 = g_xal + ((size_t)b * NC + co0) * NHW + tileBase;
        float* y1 = g_xal + ((size_t)b * NC + co1) * NHW + tileBase;
        #pragma unroll
        for (int nt = 0; nt < 8; nt++) {
            const int pix = nt * 8 + 2 * r;
            float v0 = acc[mt][nt][0] + tb0, v1 = acc[mt][nt][1] + tb0;
            float v2 = acc[mt][nt][2] + tb1, v3 = acc[mt][nt][3] + tb1;
            *(float2*)&y0[pix] = make_float2(v0 * sigmoidf_(v0), v1 * sigmoidf_(v1));
            *(float2*)&y1[pix] = make_float2(v2 * sigmoidf_(v2), v3 * sigmoidf_(v3));
        }
    }
}

// ---------------------------------------------------------------------------
// Kernel 2: per-(b,c) global sum/max + 4x4 local pool sums (static bins)
// ---------------------------------------------------------------------------
__global__ __launch_bounds__(160) void pool_kernel() {
    const int bc = blockIdx.x;
    const float4* plane = (const float4*)(g_xal + (size_t)bc * NHW);
    const int t = threadIdx.x, wb = t & 3, hr = t >> 2;

    float cell[4];
    float gmx = -1e30f;
    #pragma unroll
    for (int gy = 0; gy < 4; gy++) {
        const float4* rp = plane + ((gy * 40 + hr) * NW + wb * 40) / 4;
        float s = 0.f;
        #pragma unroll
        for (int i = 0; i < 10; i++) {
            float4 v = rp[i];
            s += (v.x + v.y) + (v.z + v.w);
            gmx = fmaxf(gmx, fmaxf(fmaxf(v.x, v.y), fmaxf(v.z, v.w)));
        }
        cell[gy] = s;
    }
    float gs = (cell[0] + cell[1]) + (cell[2] + cell[3]);

    #pragma unroll
    for (int o = 4; o <= 16; o <<= 1)
        #pragma unroll
        for (int gy = 0; gy < 4; gy++)
            cell[gy] += __shfl_xor_sync(0xffffffffu, cell[gy], o);
    #pragma unroll
    for (int o = 1; o <= 16; o <<= 1) {
        gs += __shfl_xor_sync(0xffffffffu, gs, o);
        gmx = fmaxf(gmx, __shfl_xor_sync(0xffffffffu, gmx, o));
    }

    __shared__ float sC[5][4][4], sS[5], sM[5];
    const int w = t >> 5, lanei = t & 31;
    if (lanei < 4) {
        #pragma unroll
        for (int gy = 0; gy < 4; gy++) sC[w][gy][lanei] = cell[gy];
    }
    if (lanei == 0) { sS[w] = gs; sM[w] = gmx; }
    __syncthreads();
    if (t < 16) {
        float v = 0.f;
        #pragma unroll
        for (int w2 = 0; w2 < 5; w2++) v += sC[w2][t >> 2][t & 3];
        g_lsum[bc * 16 + t] = v;
    }
    if (t == 0) {
        float S = 0.f, M = -1e30f;
        #pragma unroll
        for (int w2 = 0; w2 < 5; w2++) { S += sS[w2]; M = fmaxf(M, sM[w2]); }
        g_gsum[bc] = S;
        g_gmax[bc] = M;
    }
}

// ---------------------------------------------------------------------------
// Kernel 3: pre-average offset conv2 weights over the 49 output taps
// ---------------------------------------------------------------------------
__global__ void prep_kernel(const float* __restrict__ off_w2,
                            const float* __restrict__ off_b2) {
    const int i = threadIdx.x;
    if (i < 288) {
        const int d = i / 144, rest = i % 144;
        float s = 0.f;
        for (int j = 0; j < 49; j++) s += off_w2[(d * 49 + j) * 144 + rest];
        g_wavg[i] = s * (1.f / 49.f);
    }
    if (i < 2) {
        float s = 0.f;
        for (int j = 0; j < 49; j++) s += off_b2[i * 49 + j];
        g_bavg[i] = s * (1.f / 49.f);
    }
}

// ---------------------------------------------------------------------------
// Kernel 4: channel attention -> g_ca
// ---------------------------------------------------------------------------
__global__ __launch_bounds__(256) void ca_kernel(
    const float* __restrict__ mlp_w1, const float* __restrict__ mlp_w2,
    const float* __restrict__ loc_w1, const float* __restrict__ loc_w2,
    const float* __restrict__ fusion_w)
{
    const int b = blockIdx.x, tid = threadIdx.x;
    __shared__ float avg[256], mxv[256];
    __shared__ float h1[32], hpart[32][8], hcell[16][16], hbar[16];

    avg[tid] = g_gsum[b * NC + tid] * (1.f / (float)NHW);
    mxv[tid] = g_gmax[b * NC + tid];
    __syncthreads();

    {
        const int m = tid >> 3, part = tid & 7;
        const int mm = m & 15;
        const float* src = (m < 16) ? avg : mxv;
        float a = 0.f;
        #pragma unroll 8
        for (int c = part * 32; c < part * 32 + 32; c++)
            a += mlp_w1[mm * NC + c] * src[c];
        hpart[m][part] = a;
    }
    {
        const int cell = tid >> 4, m2 = tid & 15;
        float a = 0.f;
        #pragma unroll 8
        for (int c = 0; c < NC; c++)
            a += loc_w1[m2 * NC + c] * g_lsum[(b * NC + c) * 16 + cell];
        hcell[cell][m2] = fmaxf(a * (1.f / 1600.f), 0.f);
    }
    __syncthreads();
    if (tid < 32) {
        float a = 0.f;
        #pragma unroll
        for (int p = 0; p < 8; p++) a += hpart[tid][p];
        h1[tid] = fmaxf(a, 0.f);
    }
    if (tid >= 32 && tid < 48) {
        float s = 0.f;
        #pragma unroll
        for (int cell = 0; cell < 16; cell++) s += hcell[cell][tid - 32];
        hbar[tid - 32] = s * (1.f / 16.f);
    }
    __syncthreads();

    float ga = 0.f, la = 0.f;
    #pragma unroll
    for (int m = 0; m < 16; m++) {
        ga += mlp_w2[tid * 16 + m] * (h1[m] + h1[16 + m]);
        la += loc_w2[tid * 16 + m] * hbar[m];
    }
    const float alpha = sigmoidf_(fusion_w[0]);
    g_ca[b * NC + tid] = sigmoidf_(alpha * ga + (1.f - alpha) * la);
}

// ---------------------------------------------------------------------------
// Kernel 5: sf = [mean_c(ca*x), max_c(ca*x)]  (float4)
// ---------------------------------------------------------------------------
__global__ __launch_bounds__(256) void sf_kernel() {
    const int b = blockIdx.y;
    const int p4 = blockIdx.x * 256 + threadIdx.x;
    const float4* xb = (const float4*)(g_xal + (size_t)b * NC * NHW);
    const float* cab = g_ca + b * NC;
    float4 s = make_float4(0.f, 0.f, 0.f, 0.f);
    float4 mx = make_float4(-1e30f, -1e30f, -1e30f, -1e30f);
    #pragma unroll 4
    for (int c = 0; c < NC; c++) {
        const float cc = cab[c];
        float4 v = xb[(size_t)c * (NHW / 4) + p4];
        v.x *= cc; v.y *= cc; v.z *= cc; v.w *= cc;
        s.x += v.x; s.y += v.y; s.z += v.z; s.w += v.w;
        mx.x = fmaxf(mx.x, v.x); mx.y = fmaxf(mx.y, v.y);
        mx.z = fmaxf(mx.z, v.z); mx.w = fmaxf(mx.w, v.w);
    }
    const float inv = 1.f / (float)NC;
    s.x *= inv; s.y *= inv; s.z *= inv; s.w *= inv;
    ((float4*)(g_sf + (size_t)b * 2 * NHW))[p4] = s;
    ((float4*)(g_sf + (size_t)b * 2 * NHW + NHW))[p4] = mx;
}

// ---------------------------------------------------------------------------
// Kernel 6: offset conv1: 3x3, 2->16 + BN + ReLU
// ---------------------------------------------------------------------------
__global__ __launch_bounds__(256) void off1_kernel(
    const float* __restrict__ w1, const float* __restrict__ gg,
    const float* __restrict__ bt, const float* __restrict__ mm,
    const float* __restrict__ vv)
{
    const int p = blockIdx.x * blockDim.x + threadIdx.x;
    const int co = blockIdx.y, b = blockIdx.z;
    const int h = p / NW, w = p % NW;
    const float* sfb = g_sf + (size_t)b * 2 * NHW;
    float acc = 0.f;
    #pragma unroll
    for (int ci = 0; ci < 2; ci++) {
        #pragma unroll
        for (int ky = 0; ky < 3; ky++) {
            const int hy = h + ky - 1;
            if (hy < 0 || hy >= NH) continue;
            #pragma unroll
            for (int kx = 0; kx < 3; kx++) {
                const int wx = w + kx - 1;
                if (wx < 0 || wx >= NW) continue;
                acc += w1[((co * 2 + ci) * 3 + ky) * 3 + kx] *
                       sfb[ci * NHW + hy * NW + wx];
            }
        }
    }
    const float sc = gg[co] * rsqrtf(vv[co] + BN_EPS);
    const float tb = bt[co] - mm[co] * sc;
    g_o1[((size_t)b * 16 + co) * NHW + p] = fmaxf(acc * sc + tb, 0.f);
}

// ---------------------------------------------------------------------------
// Kernel 7: averaged offset conv2 + tanh*0.5 + grid + bilinear sample
// ---------------------------------------------------------------------------
__global__ __launch_bounds__(256) void off2_sample_kernel() {
    const int b = blockIdx.y;
    const int p = blockIdx.x * blockDim.x + threadIdx.x;
    const int h = p / NW, w = p % NW;
    const float* o1b = g_o1 + (size_t)b * 16 * NHW;

    float off[2];
    #pragma unroll
    for (int d = 0; d < 2; d++) {
        float acc = g_bavg[d];
        for (int ci = 0; ci < 16; ci++) {
            #pragma unroll
            for (int ky = 0; ky < 3; ky++) {
                const int hy = h + ky - 1;
                if (hy < 0 || hy >= NH) continue;
                #pragma unroll
                for (int kx = 0; kx < 3; kx++) {
                    const int wx = w + kx - 1;
                    if (wx < 0 || wx >= NW) continue;
                    acc += g_wavg[(d * 16 + ci) * 9 + ky * 3 + kx] *
                           o1b[(size_t)ci * NHW + hy * NW + wx];
                }
            }
        }
        off[d] = tanhf(acc) * 0.5f;
    }

    const float bx = -1.f + 2.f * (float)w / 159.f;
    const float by = -1.f + 2.f * (float)h / 159.f;
    const float gx = fminf(fmaxf(bx + off[0], -1.f), 1.f);
    const float gy = fminf(fmaxf(by + off[1], -1.f), 1.f);

    const float fx = (gx + 1.f) * ((float)NW * 0.5f) - 0.5f;
    const float fy = (gy + 1.f) * ((float)NH * 0.5f) - 0.5f;
    const float x0f = floorf(fx), y0f = floorf(fy);
    const int x0 = (int)x0f, y0 = (int)y0f;
    const float wx = fx - x0f, wy = fy - y0f;

    const float* sfb = g_sf + (size_t)b * 2 * NHW;
    float out0 = 0.f, out1 = 0.f;
    #pragma unroll
    for (int dy = 0; dy < 2; dy++) {
        const int yy = y0 + dy;
        if (yy < 0 || yy >= NH) continue;
        const float wgy = dy ? wy : (1.f - wy);
        #pragma unroll
        for (int dx = 0; dx < 2; dx++) {
            const int xx = x0 + dx;
            if (xx < 0 || xx >= NW) continue;
            const float wt = wgy * (dx ? wx : (1.f - wx));
            out0 += wt * sfb[yy * NW + xx];
            out1 += wt * sfb[NHW + yy * NW + xx];
        }
    }
    g_sampled[(size_t)b * 2 * NHW + p] = out0;
    g_sampled[(size_t)b * 2 * NHW + NHW + p] = out1;
}

// ---------------------------------------------------------------------------
// Kernel 8: 7x7 conv (2->1) over sampled + sigmoid -> g_sa
// ---------------------------------------------------------------------------
__global__ __launch_bounds__(256) void sa_kernel(const float* __restrict__ attn_w) {
    const int b = blockIdx.y;
    const int p = blockIdx.x * blockDim.x + threadIdx.x;
    const int h = p / NW, w = p % NW;
    const float* sm = g_sampled + (size_t)b * 2 * NHW;
    float acc = 0.f;
    #pragma unroll
    for (int ci = 0; ci < 2; ci++) {
        #pragma unroll
        for (int ky = 0; ky < 7; ky++) {
            const int hy = h + ky - 3;
            if (hy < 0 || hy >= NH) continue;
            #pragma unroll
            for (int kx = 0; kx < 7; kx++) {
                const int wx = w + kx - 3;
                if (wx < 0 || wx >= NW) continue;
                acc += attn_w[(ci * 7 + ky) * 7 + kx] *
                       sm[ci * NHW + hy * NW + wx];
            }
        }
    }
    g_sa[b * NHW + p] = sigmoidf_(acc);
}

// ---------------------------------------------------------------------------
// Kernel 9: out = sa * ca * x_aligned
// ---------------------------------------------------------------------------
__global__ __launch_bounds__(256) void final_kernel(float* __restrict__ out) {
    const unsigned idx4 = blockIdx.x * blockDim.x + threadIdx.x;
    const unsigned total4 = (unsigned)NB * NC * NHW / 4;
    if (idx4 >= total4) return;
    const unsigned e = idx4 * 4;
    const unsigned p = e % NHW;
    const unsigned c = (e / NHW) % NC;
    const unsigned b = e / (NHW * NC);
    const float4 xv = *reinterpret_cast<const float4*>(&g_xal[e]);
    const float4 sav = *reinterpret_cast<const float4*>(&g_sa[b * NHW + p]);
    const float cc = g_ca[b * NC + c];
    float4 r;
    r.x = xv.x * sav.x * cc;
    r.y = xv.y * sav.y * cc;
    r.z = xv.z * sav.z * cc;
    r.w = xv.w * sav.w * cc;
    *reinterpret_cast<float4*>(&out[e]) = r;
}

// ---------------------------------------------------------------------------
extern "C" void kernel_launch(void* const* d_in, const int* in_sizes, int n_in,
                              void* d_out, int out_size) {
    const float* x       = (const float*)d_in[0];
    const float* align_w = (const float*)d_in[1];
    const float* align_g = (const float*)d_in[2];
    const float* align_b = (const float*)d_in[3];
    const float* align_m = (const float*)d_in[4];
    const float* align_v = (const float*)d_in[5];
    const float* mlp_w1  = (const float*)d_in[6];
    const float* mlp_w2  = (const float*)d_in[7];
    const float* loc_w1  = (const float*)d_in[8];
    const float* loc_w2  = (const float*)d_in[9];
    const float* fusion  = (const float*)d_in[10];
    const float* off_w1  = (const float*)d_in[11];
    const float* off_g   = (const float*)d_in[12];
    const float* off_bt  = (const float*)d_in[13];
    const float* off_m   = (const float*)d_in[14];
    const float* off_v   = (const float*)d_in[15];
    const float* off_w2  = (const float*)d_in[16];
    const float* off_b2  = (const float*)d_in[17];
    const float* attn_w  = (const float*)d_in[18];
    float* out = (float*)d_out;

    static bool attrSet = false;
    if (!attrSet) {
        cudaFuncSetAttribute(gemm_kernel,
                             cudaFuncAttributeMaxDynamicSharedMemorySize,
                             DSMEM_U32 * 4);
        attrSet = true;
    }

    wpack_kernel<<<128, 256>>>(align_w, align_g, align_b, align_m, align_v);
    prep_kernel<<<1, 288>>>(off_w2, off_b2);

    dim3 gGemm(NTILES, NB);
    gemm_kernel<<<gGemm, 256, DSMEM_U32 * 4>>>(x);

    pool_kernel<<<NB * NC, 160>>>();
    ca_kernel<<<NB, 256>>>(mlp_w1, mlp_w2, loc_w1, loc_w2, fusion);

    dim3 gPix4(NHW / 4 / 256, NB);
    sf_kernel<<<gPix4, 256>>>();

    dim3 gPix(NHW / 256, NB);
    dim3 gOff1(NHW / 256, 16, NB);
    off1_kernel<<<gOff1, 256>>>(off_w1, off_g, off_bt, off_m, off_v);
    off2_sample_kernel<<<gPix, 256>>>();
    sa_kernel<<<gPix, 256>>>(attn_w);

    const unsigned total4 = (unsigned)NB * NC * NHW / 4;
    final_kernel<<<(total4 + 255) / 256, 256>>>(out);
}

// round 8
// speedup vs baseline: 1.7542x; 1.0826x over previous
#include <cuda_runtime.h>
#include <cuda_fp16.h>
#include <cstdint>

static constexpr int NB = 8;
static constexpr int NC = 256;
static constexpr int NH = 160;
static constexpr int NW = 160;
static constexpr int NHW = NH * NW;           // 25600
static constexpr int TILE_N = 64;
static constexpr int NTILES = NHW / TILE_N;   // 400
static constexpr float BN_EPS = 1e-5f;

// dynamic smem layout (u32 units):
//  Wh0[5120] Wl0[5120] Wh1[5120] Wl1[5120]  (stages of 10240 at 0)
//  X stages at 20480: per stage 2560 = Xh[1280] + Xs[1280]
static constexpr int SM_X = 20480;
static constexpr int DSMEM_U32 = 25600;       // 100 KB

// ---------------- scratch (static device globals) --------------------------
__device__ float g_xal[(size_t)NB * NC * NHW];
__device__ uint32_t g_wph[NC * 128];     // packed fp16x2 (k-pairs) scaled W, hi
__device__ uint32_t g_wpl[NC * 128];     // lo residual * 2^10
__device__ float g_bias[NC];
__device__ float g_gsum[NB * NC];
__device__ float g_gmax[NB * NC];
__device__ float g_lsum[NB * NC * 16];
__device__ float g_ca[NB * NC];
__device__ float g_sf[NB * 2 * NHW];
__device__ float g_o1[NB * 16 * NHW];
__device__ float g_sampled[NB * 2 * NHW];
__device__ float g_sa[NB * NHW];
__device__ float g_wavg[2 * 16 * 9];
__device__ float g_bavg[2];

__device__ __forceinline__ float sigmoidf_(float x) {
    return 1.f / (1.f + __expf(-x));
}
__device__ __forceinline__ uint32_t packh(__half a, __half b) {
    __half2 t = __halves2half2(a, b);     // low = a
    return *reinterpret_cast<uint32_t*>(&t);
}
__device__ __forceinline__ void mma16816h(float* c, const uint32_t* a,
                                          uint32_t b0, uint32_t b1) {
    asm volatile(
        "mma.sync.aligned.m16n8k16.row.col.f32.f16.f16.f32 "
        "{%0,%1,%2,%3}, {%4,%5,%6,%7}, {%8,%9}, {%0,%1,%2,%3};"
        : "+f"(c[0]), "+f"(c[1]), "+f"(c[2]), "+f"(c[3])
        : "r"(a[0]), "r"(a[1]), "r"(a[2]), "r"(a[3]), "r"(b0), "r"(b1));
}
__device__ __forceinline__ void ldsm4(uint32_t* d, uint32_t addr) {
    asm volatile(
        "ldmatrix.sync.aligned.m8n8.x4.shared.b16 {%0,%1,%2,%3}, [%4];"
        : "=r"(d[0]), "=r"(d[1]), "=r"(d[2]), "=r"(d[3]) : "r"(addr));
}

// ---------------------------------------------------------------------------
// Kernel 0: pack BN-scaled weights into fp16 hi + (lo * 2^10) k-pairs
// ---------------------------------------------------------------------------
__global__ __launch_bounds__(256) void wpack_kernel(
    const float* __restrict__ w, const float* __restrict__ g,
    const float* __restrict__ bb, const float* __restrict__ m,
    const float* __restrict__ v)
{
    const int id = blockIdx.x * 256 + threadIdx.x;   // 0..32767
    const int co = id >> 7, kp = id & 127;
    const float sc = g[co] * rsqrtf(v[co] + BN_EPS);
    const float w0 = w[co * 256 + 2 * kp] * sc;
    const float w1 = w[co * 256 + 2 * kp + 1] * sc;
    const __half h0 = __float2half_rn(w0);
    const __half h1 = __float2half_rn(w1);
    const __half l0 = __float2half_rn((w0 - __half2float(h0)) * 1024.f);
    const __half l1 = __float2half_rn((w1 - __half2float(h1)) * 1024.f);
    g_wph[co * 128 + kp] = packh(h0, h1);
    g_wpl[co * 128 + kp] = packh(l0, l1);
    if (kp == 0) g_bias[co] = bb[co] - m[co] * sc;
}

// ---------------------------------------------------------------------------
// Kernel 1: tensor-core GEMM, CTA = [256 co x 64 px], K=256, fp16 2-pass:
//   acc = Wh*Xh + (Wl*2^10)*(Xh*2^-10)   (exact-W x fp16-rounded-X)
//   occupancy 2, W+X fully double-buffered, ONE sync per K-chunk.
// ---------------------------------------------------------------------------
__global__ void __launch_bounds__(256, 2) gemm_kernel(const float* __restrict__ X)
{
    extern __shared__ uint32_t sm[];
    const int tile = blockIdx.x, b = blockIdx.y;
    const int tileBase = tile * TILE_N;
    const int t = threadIdx.x, lane = t & 31, warp = t >> 5;   // warp = warpM 0..7
    const int q = lane >> 2, r = lane & 3;
    const float* Xb = X + (size_t)b * NC * NHW + tileBase;
    const int kp = t & 15, pg = t >> 4;       // X staging: kpair, pixel group of 4

    const uint32_t smBase = (uint32_t)__cvta_generic_to_shared(sm);
    // ldmatrix per-lane offsets (u32 units)
    const uint32_t aOff = (uint32_t)((warp * 32 + (lane & 15)) * 20 + ((lane >> 4) << 2));
    const uint32_t bOff = (uint32_t)((((lane & 16) ? 8 : 0) + (lane & 7)) * 20
                                     + ((lane & 8) ? 4 : 0));

    float acc[2][8][4];
    #pragma unroll
    for (int i = 0; i < 2; i++)
        #pragma unroll
        for (int j = 0; j < 8; j++)
            #pragma unroll
            for (int k = 0; k < 4; k++) acc[i][j][k] = 0.f;

    float4 xr0, xr1;

    auto cpW = [&](int c, int s) {
        const uint32_t dWh = smBase + (uint32_t)(s * 10240) * 4u;
        const uint32_t dWl = dWh + 5120u * 4u;
        #pragma unroll
        for (int i = 0; i < 4; i++) {
            const int id = i * 256 + t;
            const int row = id >> 2, grp = id & 3;
            const uint32_t off = (uint32_t)(row * 20 + grp * 4) * 4u;
            const uint32_t* s1 = &g_wph[row * 128 + c * 16 + grp * 4];
            const uint32_t* s2 = &g_wpl[row * 128 + c * 16 + grp * 4];
            asm volatile("cp.async.cg.shared.global [%0], [%1], 16;" :: "r"(dWh + off), "l"(s1));
            asm volatile("cp.async.cg.shared.global [%0], [%1], 16;" :: "r"(dWl + off), "l"(s2));
        }
        asm volatile("cp.async.commit_group;");
    };
    auto ldgX = [&](int c) {
        const float* x0 = Xb + (size_t)(c * 32 + 2 * kp) * NHW + pg * 4;
        xr0 = *(const float4*)x0;
        xr1 = *(const float4*)(x0 + NHW);
    };
    auto stsX = [&](int sx) {
        float e0[4] = {xr0.x, xr0.y, xr0.z, xr0.w};
        float e1[4] = {xr1.x, xr1.y, xr1.z, xr1.w};
        const int base = SM_X + sx * 2560;
        #pragma unroll
        for (int j = 0; j < 4; j++) {
            const __half h0 = __float2half_rn(e0[j]);
            const __half h1 = __float2half_rn(e1[j]);
            // exact 2^-10 scaling of representable halves
            const __half s0 = __float2half_rn(__half2float(h0) * 9.765625e-4f);
            const __half s1 = __float2half_rn(__half2float(h1) * 9.765625e-4f);
            sm[base + (pg * 4 + j) * 20 + kp]        = packh(h0, h1);
            sm[base + 1280 + (pg * 4 + j) * 20 + kp] = packh(s0, s1);
        }
    };

    // ---- prologue ----
    cpW(0, 0);
    ldgX(0);
    stsX(0);
    ldgX(1);
    asm volatile("cp.async.wait_group 0;");
    __syncthreads();

    for (int c = 0; c < 8; c++) {
        if (c < 7) {
            stsX((c + 1) & 1);          // from regs of X(c+1)
            cpW(c + 1, (c + 1) & 1);
        }
        if (c < 6) ldgX(c + 2);

        const uint32_t whB = smBase + (uint32_t)((c & 1) * 10240) * 4u;
        const uint32_t wlB = whB + 5120u * 4u;
        const uint32_t xhB = smBase + (uint32_t)(SM_X + (c & 1) * 2560) * 4u;
        const uint32_t xsB = xhB + 1280u * 4u;

        #pragma unroll
        for (int ks = 0; ks < 2; ks++) {
            uint32_t Ah[2][4], Al[2][4];
            #pragma unroll
            for (int mt = 0; mt < 2; mt++) {
                ldsm4(Ah[mt], whB + (aOff + mt * 320 + ks * 8) * 4u);
                ldsm4(Al[mt], wlB + (aOff + mt * 320 + ks * 8) * 4u);
            }
            #pragma unroll
            for (int np = 0; np < 4; np++) {
                uint32_t B0[4], Bs[4];
                ldsm4(B0, xhB + (bOff + np * 320 + ks * 8) * 4u);
                ldsm4(Bs, xsB + (bOff + np * 320 + ks * 8) * 4u);
                #pragma unroll
                for (int j = 0; j < 2; j++)
                    #pragma unroll
                    for (int mt = 0; mt < 2; mt++) {
                        mma16816h(acc[mt][np * 2 + j], Ah[mt], B0[2 * j], B0[2 * j + 1]);
                        mma16816h(acc[mt][np * 2 + j], Al[mt], Bs[2 * j], Bs[2 * j + 1]);
                    }
            }
        }
        if (c < 7) asm volatile("cp.async.wait_group 0;");
        __syncthreads();
    }

    // ---- epilogue: bias + SiLU + store ----
    #pragma unroll
    for (int mt = 0; mt < 2; mt++) {
        const int co0 = warp * 32 + mt * 16 + q;
        const int co1 = co0 + 8;
        const float tb0 = g_bias[co0], tb1 = g_bias[co1];
        float* y0 = g_xal + ((size_t)b * NC + co0) * NHW + tileBase;
        float* y1 = g_xal + ((size_t)b * NC + co1) * NHW + tileBase;
        #pragma unroll
        for (int nt = 0; nt < 8; nt++) {
            const int pix = nt * 8 + 2 * r;
            float v0 = acc[mt][nt][0] + tb0, v1 = acc[mt][nt][1] + tb0;
            float v2 = acc[mt][nt][2] + tb1, v3 = acc[mt][nt][3] + tb1;
            *(float2*)&y0[pix] = make_float2(v0 * sigmoidf_(v0), v1 * sigmoidf_(v1));
            *(float2*)&y1[pix] = make_float2(v2 * sigmoidf_(v2), v3 * sigmoidf_(v3));
        }
    }
}

// ---------------------------------------------------------------------------
// Kernel 2: per-(b,c) global sum/max + 4x4 local pool sums (static bins)
// ---------------------------------------------------------------------------
__global__ __launch_bounds__(160) void pool_kernel() {
    const int bc = blockIdx.x;
    const float4* plane = (const float4*)(g_xal + (size_t)bc * NHW);
    const int t = threadIdx.x, wb = t & 3, hr = t >> 2;

    float cell[4];
    float gmx = -1e30f;
    #pragma unroll
    for (int gy = 0; gy < 4; gy++) {
        const float4* rp = plane + ((gy * 40 + hr) * NW + wb * 40) / 4;
        float s = 0.f;
        #pragma unroll
        for (int i = 0; i < 10; i++) {
            float4 v = rp[i];
            s += (v.x + v.y) + (v.z + v.w);
            gmx = fmaxf(gmx, fmaxf(fmaxf(v.x, v.y), fmaxf(v.z, v.w)));
        }
        cell[gy] = s;
    }
    float gs = (cell[0] + cell[1]) + (cell[2] + cell[3]);

    #pragma unroll
    for (int o = 4; o <= 16; o <<= 1)
        #pragma unroll
        for (int gy = 0; gy < 4; gy++)
            cell[gy] += __shfl_xor_sync(0xffffffffu, cell[gy], o);
    #pragma unroll
    for (int o = 1; o <= 16; o <<= 1) {
        gs += __shfl_xor_sync(0xffffffffu, gs, o);
        gmx = fmaxf(gmx, __shfl_xor_sync(0xffffffffu, gmx, o));
    }

    __shared__ float sC[5][4][4], sS[5], sM[5];
    const int w = t >> 5, lanei = t & 31;
    if (lanei < 4) {
        #pragma unroll
        for (int gy = 0; gy < 4; gy++) sC[w][gy][lanei] = cell[gy];
    }
    if (lanei == 0) { sS[w] = gs; sM[w] = gmx; }
    __syncthreads();
    if (t < 16) {
        float v = 0.f;
        #pragma unroll
        for (int w2 = 0; w2 < 5; w2++) v += sC[w2][t >> 2][t & 3];
        g_lsum[bc * 16 + t] = v;
    }
    if (t == 0) {
        float S = 0.f, M = -1e30f;
        #pragma unroll
        for (int w2 = 0; w2 < 5; w2++) { S += sS[w2]; M = fmaxf(M, sM[w2]); }
        g_gsum[bc] = S;
        g_gmax[bc] = M;
    }
}

// ---------------------------------------------------------------------------
// Kernel 3: pre-average offset conv2 weights over the 49 output taps
// ---------------------------------------------------------------------------
__global__ void prep_kernel(const float* __restrict__ off_w2,
                            const float* __restrict__ off_b2) {
    const int i = threadIdx.x;
    if (i < 288) {
        const int d = i / 144, rest = i % 144;
        float s = 0.f;
        for (int j = 0; j < 49; j++) s += off_w2[(d * 49 + j) * 144 + rest];
        g_wavg[i] = s * (1.f / 49.f);
    }
    if (i < 2) {
        float s = 0.f;
        for (int j = 0; j < 49; j++) s += off_b2[i * 49 + j];
        g_bavg[i] = s * (1.f / 49.f);
    }
}

// ---------------------------------------------------------------------------
// Kernel 4: channel attention -> g_ca
// ---------------------------------------------------------------------------
__global__ __launch_bounds__(256) void ca_kernel(
    const float* __restrict__ mlp_w1, const float* __restrict__ mlp_w2,
    const float* __restrict__ loc_w1, const float* __restrict__ loc_w2,
    const float* __restrict__ fusion_w)
{
    const int b = blockIdx.x, tid = threadIdx.x;
    __shared__ float avg[256], mxv[256];
    __shared__ float h1[32], hpart[32][8], hcell[16][16], hbar[16];

    avg[tid] = g_gsum[b * NC + tid] * (1.f / (float)NHW);
    mxv[tid] = g_gmax[b * NC + tid];
    __syncthreads();

    {
        const int m = tid >> 3, part = tid & 7;
        const int mm = m & 15;
        const float* src = (m < 16) ? avg : mxv;
        float a = 0.f;
        #pragma unroll 8
        for (int c = part * 32; c < part * 32 + 32; c++)
            a += mlp_w1[mm * NC + c] * src[c];
        hpart[m][part] = a;
    }
    {
        const int cell = tid >> 4, m2 = tid & 15;
        float a = 0.f;
        #pragma unroll 8
        for (int c = 0; c < NC; c++)
            a += loc_w1[m2 * NC + c] * g_lsum[(b * NC + c) * 16 + cell];
        hcell[cell][m2] = fmaxf(a * (1.f / 1600.f), 0.f);
    }
    __syncthreads();
    if (tid < 32) {
        float a = 0.f;
        #pragma unroll
        for (int p = 0; p < 8; p++) a += hpart[tid][p];
        h1[tid] = fmaxf(a, 0.f);
    }
    if (tid >= 32 && tid < 48) {
        float s = 0.f;
        #pragma unroll
        for (int cell = 0; cell < 16; cell++) s += hcell[cell][tid - 32];
        hbar[tid - 32] = s * (1.f / 16.f);
    }
    __syncthreads();

    float ga = 0.f, la = 0.f;
    #pragma unroll
    for (int m = 0; m < 16; m++) {
        ga += mlp_w2[tid * 16 + m] * (h1[m] + h1[16 + m]);
        la += loc_w2[tid * 16 + m] * hbar[m];
    }
    const float alpha = sigmoidf_(fusion_w[0]);
    g_ca[b * NC + tid] = sigmoidf_(alpha * ga + (1.f - alpha) * la);
}

// ---------------------------------------------------------------------------
// Kernel 5: sf = [mean_c(ca*x), max_c(ca*x)]  (float4)
// ---------------------------------------------------------------------------
__global__ __launch_bounds__(256) void sf_kernel() {
    const int b = blockIdx.y;
    const int p4 = blockIdx.x * 256 + threadIdx.x;
    const float4* xb = (const float4*)(g_xal + (size_t)b * NC * NHW);
    const float* cab = g_ca + b * NC;
    float4 s = make_float4(0.f, 0.f, 0.f, 0.f);
    float4 mx = make_float4(-1e30f, -1e30f, -1e30f, -1e30f);
    #pragma unroll 4
    for (int c = 0; c < NC; c++) {
        const float cc = cab[c];
        float4 v = xb[(size_t)c * (NHW / 4) + p4];
        v.x *= cc; v.y *= cc; v.z *= cc; v.w *= cc;
        s.x += v.x; s.y += v.y; s.z += v.z; s.w += v.w;
        mx.x = fmaxf(mx.x, v.x); mx.y = fmaxf(mx.y, v.y);
        mx.z = fmaxf(mx.z, v.z); mx.w = fmaxf(mx.w, v.w);
    }
    const float inv = 1.f / (float)NC;
    s.x *= inv; s.y *= inv; s.z *= inv; s.w *= inv;
    ((float4*)(g_sf + (size_t)b * 2 * NHW))[p4] = s;
    ((float4*)(g_sf + (size_t)b * 2 * NHW + NHW))[p4] = mx;
}

// ---------------------------------------------------------------------------
// Kernel 6: offset conv1: 3x3, 2->16 + BN + ReLU
// ---------------------------------------------------------------------------
__global__ __launch_bounds__(256) void off1_kernel(
    const float* __restrict__ w1, const float* __restrict__ gg,
    const float* __restrict__ bt, const float* __restrict__ mm,
    const float* __restrict__ vv)
{
    const int p = blockIdx.x * blockDim.x + threadIdx.x;
    const int co = blockIdx.y, b = blockIdx.z;
    const int h = p / NW, w = p % NW;
    const float* sfb = g_sf + (size_t)b * 2 * NHW;
    float acc = 0.f;
    #pragma unroll
    for (int ci = 0; ci < 2; ci++) {
        #pragma unroll
        for (int ky = 0; ky < 3; ky++) {
            const int hy = h + ky - 1;
            if (hy < 0 || hy >= NH) continue;
            #pragma unroll
            for (int kx = 0; kx < 3; kx++) {
                const int wx = w + kx - 1;
                if (wx < 0 || wx >= NW) continue;
                acc += w1[((co * 2 + ci) * 3 + ky) * 3 + kx] *
                       sfb[ci * NHW + hy * NW + wx];
            }
        }
    }
    const float sc = gg[co] * rsqrtf(vv[co] + BN_EPS);
    const float tb = bt[co] - mm[co] * sc;
    g_o1[((size_t)b * 16 + co) * NHW + p] = fmaxf(acc * sc + tb, 0.f);
}

// ---------------------------------------------------------------------------
// Kernel 7: averaged offset conv2 + tanh*0.5 + grid + bilinear sample
// ---------------------------------------------------------------------------
__global__ __launch_bounds__(256) void off2_sample_kernel() {
    const int b = blockIdx.y;
    const int p = blockIdx.x * blockDim.x + threadIdx.x;
    const int h = p / NW, w = p % NW;
    const float* o1b = g_o1 + (size_t)b * 16 * NHW;

    float off[2];
    #pragma unroll
    for (int d = 0; d < 2; d++) {
        float acc = g_bavg[d];
        for (int ci = 0; ci < 16; ci++) {
            #pragma unroll
            for (int ky = 0; ky < 3; ky++) {
                const int hy = h + ky - 1;
                if (hy < 0 || hy >= NH) continue;
                #pragma unroll
                for (int kx = 0; kx < 3; kx++) {
                    const int wx = w + kx - 1;
                    if (wx < 0 || wx >= NW) continue;
                    acc += g_wavg[(d * 16 + ci) * 9 + ky * 3 + kx] *
                           o1b[(size_t)ci * NHW + hy * NW + wx];
                }
            }
        }
        off[d] = tanhf(acc) * 0.5f;
    }

    const float bx = -1.f + 2.f * (float)w / 159.f;
    const float by = -1.f + 2.f * (float)h / 159.f;
    const float gx = fminf(fmaxf(bx + off[0], -1.f), 1.f);
    const float gy = fminf(fmaxf(by + off[1], -1.f), 1.f);

    const float fx = (gx + 1.f) * ((float)NW * 0.5f) - 0.5f;
    const float fy = (gy + 1.f) * ((float)NH * 0.5f) - 0.5f;
    const float x0f = floorf(fx), y0f = floorf(fy);
    const int x0 = (int)x0f, y0 = (int)y0f;
    const float wx = fx - x0f, wy = fy - y0f;

    const float* sfb = g_sf + (size_t)b * 2 * NHW;
    float out0 = 0.f, out1 = 0.f;
    #pragma unroll
    for (int dy = 0; dy < 2; dy++) {
        const int yy = y0 + dy;
        if (yy < 0 || yy >= NH) continue;
        const float wgy = dy ? wy : (1.f - wy);
        #pragma unroll
        for (int dx = 0; dx < 2; dx++) {
            const int xx = x0 + dx;
            if (xx < 0 || xx >= NW) continue;
            const float wt = wgy * (dx ? wx : (1.f - wx));
            out0 += wt * sfb[yy * NW + xx];
            out1 += wt * sfb[NHW + yy * NW + xx];
        }
    }
    g_sampled[(size_t)b * 2 * NHW + p] = out0;
    g_sampled[(size_t)b * 2 * NHW + NHW + p] = out1;
}

// ---------------------------------------------------------------------------
// Kernel 8: 7x7 conv (2->1) over sampled + sigmoid -> g_sa
// ---------------------------------------------------------------------------
__global__ __launch_bounds__(256) void sa_kernel(const float* __restrict__ attn_w) {
    const int b = blockIdx.y;
    const int p = blockIdx.x * blockDim.x + threadIdx.x;
    const int h = p / NW, w = p % NW;
    const float* sm = g_sampled + (size_t)b * 2 * NHW;
    float acc = 0.f;
    #pragma unroll
    for (int ci = 0; ci < 2; ci++) {
        #pragma unroll
        for (int ky = 0; ky < 7; ky++) {
            const int hy = h + ky - 3;
            if (hy < 0 || hy >= NH) continue;
            #pragma unroll
            for (int kx = 0; kx < 7; kx++) {
                const int wx = w + kx - 3;
                if (wx < 0 || wx >= NW) continue;
                acc += attn_w[(ci * 7 + ky) * 7 + kx] *
                       sm[ci * NHW + hy * NW + wx];
            }
        }
    }
    g_sa[b * NHW + p] = sigmoidf_(acc);
}

// ---------------------------------------------------------------------------
// Kernel 9: out = sa * ca * x_aligned
// ---------------------------------------------------------------------------
__global__ __launch_bounds__(256) void final_kernel(float* __restrict__ out) {
    const unsigned idx4 = blockIdx.x * blockDim.x + threadIdx.x;
    const unsigned total4 = (unsigned)NB * NC * NHW / 4;
    if (idx4 >= total4) return;
    const unsigned e = idx4 * 4;
    const unsigned p = e % NHW;
    const unsigned c = (e / NHW) % NC;
    const unsigned b = e / (NHW * NC);
    const float4 xv = *reinterpret_cast<const float4*>(&g_xal[e]);
    const float4 sav = *reinterpret_cast<const float4*>(&g_sa[b * NHW + p]);
    const float cc = g_ca[b * NC + c];
    float4 r;
    r.x = xv.x * sav.x * cc;
    r.y = xv.y * sav.y * cc;
    r.z = xv.z * sav.z * cc;
    r.w = xv.w * sav.w * cc;
    *reinterpret_cast<float4*>(&out[e]) = r;
}

// ---------------------------------------------------------------------------
extern "C" void kernel_launch(void* const* d_in, const int* in_sizes, int n_in,
                              void* d_out, int out_size) {
    const float* x       = (const float*)d_in[0];
    const float* align_w = (const float*)d_in[1];
    const float* align_g = (const float*)d_in[2];
    const float* align_b = (const float*)d_in[3];
    const float* align_m = (const float*)d_in[4];
    const float* align_v = (const float*)d_in[5];
    const float* mlp_w1  = (const float*)d_in[6];
    const float* mlp_w2  = (const float*)d_in[7];
    const float* loc_w1  = (const float*)d_in[8];
    const float* loc_w2  = (const float*)d_in[9];
    const float* fusion  = (const float*)d_in[10];
    const float* off_w1  = (const float*)d_in[11];
    const float* off_g   = (const float*)d_in[12];
    const float* off_bt  = (const float*)d_in[13];
    const float* off_m   = (const float*)d_in[14];
    const float* off_v   = (const float*)d_in[15];
    const float* off_w2  = (const float*)d_in[16];
    const float* off_b2  = (const float*)d_in[17];
    const float* attn_w  = (const float*)d_in[18];
    float* out = (float*)d_out;

    static bool attrSet = false;
    if (!attrSet) {
        cudaFuncSetAttribute(gemm_kernel,
                             cudaFuncAttributeMaxDynamicSharedMemorySize,
                             DSMEM_U32 * 4);
        attrSet = true;
    }

    wpack_kernel<<<128, 256>>>(align_w, align_g, align_b, align_m, align_v);
    prep_kernel<<<1, 288>>>(off_w2, off_b2);

    dim3 gGemm(NTILES, NB);
    gemm_kernel<<<gGemm, 256, DSMEM_U32 * 4>>>(x);

    pool_kernel<<<NB * NC, 160>>>();
    ca_kernel<<<NB, 256>>>(mlp_w1, mlp_w2, loc_w1, loc_w2, fusion);

    dim3 gPix4(NHW / 4 / 256, NB);
    sf_kernel<<<gPix4, 256>>>();

    dim3 gPix(NHW / 256, NB);
    dim3 gOff1(NHW / 256, 16, NB);
    off1_kernel<<<gOff1, 256>>>(off_w1, off_g, off_bt, off_m, off_v);
    off2_sample_kernel<<<gPix, 256>>>();
    sa_kernel<<<gPix, 256>>>(attn_w);

    const unsigned total4 = (unsigned)NB * NC * NHW / 4;
    final_kernel<<<(total4 + 255) / 256, 256>>>(out);
}

// round 10
// speedup vs baseline: 1.9939x; 1.1366x over previous
#include <cuda_runtime.h>
#include <cuda_fp16.h>
#include <cstdint>

static constexpr int NB = 8;
static constexpr int NC = 256;
static constexpr int NH = 160;
static constexpr int NW = 160;
static constexpr int NHW = NH * NW;           // 25600
static constexpr int TILE_N = 64;
static constexpr int NTILES = NHW / TILE_N;   // 400
static constexpr float BN_EPS = 1e-5f;

// dynamic smem (u32 units): Wh0[5120] Wh1[5120] | X0[1280] X1[1280] = 12800 u32
static constexpr int SM_X = 10240;
static constexpr int DSMEM_U32 = 12800;       // 50 KB

// ---------------- scratch (static device globals) --------------------------
__device__ float g_xal[(size_t)NB * NC * NHW];
__device__ uint32_t g_wph[NC * 128];     // packed fp16x2 (k-pairs) BN-scaled W
__device__ float g_bias[NC];
__device__ float g_gsum[NB * NC];
__device__ float g_gmax[NB * NC];
__device__ float g_lsum[NB * NC * 16];
__device__ float g_ca[NB * NC];
__device__ float g_sf[NB * 2 * NHW];
__device__ float g_o1[NB * 16 * NHW];
__device__ float g_sampled[NB * 2 * NHW];
__device__ float g_sa[NB * NHW];
__device__ float g_wavg[2 * 16 * 9];
__device__ float g_bavg[2];

__device__ __forceinline__ float sigmoidf_(float x) {
    return 1.f / (1.f + __expf(-x));
}
__device__ __forceinline__ uint32_t packh(__half a, __half b) {
    __half2 t = __halves2half2(a, b);     // low = a
    return *reinterpret_cast<uint32_t*>(&t);
}
__device__ __forceinline__ void mma16816h(float* c, const uint32_t* a,
                                          uint32_t b0, uint32_t b1) {
    asm volatile(
        "mma.sync.aligned.m16n8k16.row.col.f32.f16.f16.f32 "
        "{%0,%1,%2,%3}, {%4,%5,%6,%7}, {%8,%9}, {%0,%1,%2,%3};"
        : "+f"(c[0]), "+f"(c[1]), "+f"(c[2]), "+f"(c[3])
        : "r"(a[0]), "r"(a[1]), "r"(a[2]), "r"(a[3]), "r"(b0), "r"(b1));
}
__device__ __forceinline__ void ldsm4(uint32_t* d, uint32_t addr) {
    asm volatile(
        "ldmatrix.sync.aligned.m8n8.x4.shared.b16 {%0,%1,%2,%3}, [%4];"
        : "=r"(d[0]), "=r"(d[1]), "=r"(d[2]), "=r"(d[3]) : "r"(addr));
}

// ---------------------------------------------------------------------------
// Kernel 0: pack BN-scaled weights into fp16 k-pairs
// ---------------------------------------------------------------------------
__global__ __launch_bounds__(256) void wpack_kernel(
    const float* __restrict__ w, const float* __restrict__ g,
    const float* __restrict__ bb, const float* __restrict__ m,
    const float* __restrict__ v)
{
    const int id = blockIdx.x * 256 + threadIdx.x;   // 0..32767
    const int co = id >> 7, kp = id & 127;
    const float sc = g[co] * rsqrtf(v[co] + BN_EPS);
    const float w0 = w[co * 256 + 2 * kp] * sc;
    const float w1 = w[co * 256 + 2 * kp + 1] * sc;
    g_wph[co * 128 + kp] = packh(__float2half_rn(w0), __float2half_rn(w1));
    if (kp == 0) g_bias[co] = bb[co] - m[co] * sc;
}

// ---------------------------------------------------------------------------
// Kernel 1: tensor-core GEMM, CTA = [256 co x 64 px], K=256, fp16 single pass.
//   occupancy 2, W+X fully double-buffered, ONE sync per K-chunk.
// ---------------------------------------------------------------------------
__global__ void __launch_bounds__(256, 2) gemm_kernel(const float* __restrict__ X)
{
    extern __shared__ uint32_t sm[];
    const int tile = blockIdx.x, b = blockIdx.y;
    const int tileBase = tile * TILE_N;
    const int t = threadIdx.x, lane = t & 31, warp = t >> 5;   // warp = warpM 0..7
    const int q = lane >> 2, r = lane & 3;
    const float* Xb = X + (size_t)b * NC * NHW + tileBase;
    const int kp = t & 15, pg = t >> 4;       // X staging: kpair, pixel group of 4

    const uint32_t smBase = (uint32_t)__cvta_generic_to_shared(sm);
    // ldmatrix per-lane offsets (u32 units); rows strided by 20 u32
    const uint32_t aOff = (uint32_t)((warp * 32 + (lane & 15)) * 20 + ((lane >> 4) << 2));
    const uint32_t bOff = (uint32_t)((((lane & 16) ? 8 : 0) + (lane & 7)) * 20
                                     + ((lane & 8) ? 4 : 0));

    float acc[2][8][4];
    #pragma unroll
    for (int i = 0; i < 2; i++)
        #pragma unroll
        for (int j = 0; j < 8; j++)
            #pragma unroll
            for (int k = 0; k < 4; k++) acc[i][j][k] = 0.f;

    float4 xr0, xr1;

    auto cpW = [&](int c, int s) {
        const uint32_t dWh = smBase + (uint32_t)(s * 5120) * 4u;
        #pragma unroll
        for (int i = 0; i < 4; i++) {
            const int id = i * 256 + t;                // 0..1023 groups of 16B
            const int row = id >> 2, grp = id & 3;
            const uint32_t off = (uint32_t)(row * 20 + grp * 4) * 4u;
            const uint32_t* s1 = &g_wph[row * 128 + c * 16 + grp * 4];
            asm volatile("cp.async.cg.shared.global [%0], [%1], 16;"
                         :: "r"(dWh + off), "l"(s1));
        }
        asm volatile("cp.async.commit_group;");
    };
    auto ldgX = [&](int c) {
        const float* x0 = Xb + (size_t)(c * 32 + 2 * kp) * NHW + pg * 4;
        xr0 = *(const float4*)x0;
        xr1 = *(const float4*)(x0 + NHW);
    };
    auto stsX = [&](int sx) {
        float e0[4] = {xr0.x, xr0.y, xr0.z, xr0.w};
        float e1[4] = {xr1.x, xr1.y, xr1.z, xr1.w};
        const int base = SM_X + sx * 1280;
        #pragma unroll
        for (int j = 0; j < 4; j++) {
            sm[base + (pg * 4 + j) * 20 + kp] =
                packh(__float2half_rn(e0[j]), __float2half_rn(e1[j]));
        }
    };

    // ---- prologue ----
    cpW(0, 0);
    ldgX(0);
    stsX(0);
    ldgX(1);
    asm volatile("cp.async.wait_group 0;");
    __syncthreads();

    for (int c = 0; c < 8; c++) {
        if (c < 7) {
            stsX((c + 1) & 1);          // from regs of X(c+1)
            cpW(c + 1, (c + 1) & 1);
        }
        if (c < 6) ldgX(c + 2);

        const uint32_t whB = smBase + (uint32_t)((c & 1) * 5120) * 4u;
        const uint32_t xhB = smBase + (uint32_t)(SM_X + (c & 1) * 1280) * 4u;

        #pragma unroll
        for (int ks = 0; ks < 2; ks++) {
            uint32_t Ah[2][4];
            #pragma unroll
            for (int mt = 0; mt < 2; mt++)
                ldsm4(Ah[mt], whB + (aOff + mt * 320 + ks * 8) * 4u);
            #pragma unroll
            for (int np = 0; np < 4; np++) {
                uint32_t B0[4];
                ldsm4(B0, xhB + (bOff + np * 320 + ks * 8) * 4u);
                #pragma unroll
                for (int j = 0; j < 2; j++)
                    #pragma unroll
                    for (int mt = 0; mt < 2; mt++)
                        mma16816h(acc[mt][np * 2 + j], Ah[mt], B0[2 * j], B0[2 * j + 1]);
            }
        }
        if (c < 7) asm volatile("cp.async.wait_group 0;");
        __syncthreads();
    }

    // ---- epilogue: bias + SiLU + store ----
    #pragma unroll
    for (int mt = 0; mt < 2; mt++) {
        const int co0 = warp * 32 + mt * 16 + q;
        const int co1 = co0 + 8;
        const float tb0 = g_bias[co0], tb1 = g_bias[co1];
        float* y0 = g_xal + ((size_t)b * NC + co0) * NHW + tileBase;
        float* y1 = g_xal + ((size_t)b * NC + co1) * NHW + tileBase;
        #pragma unroll
        for (int nt = 0; nt < 8; nt++) {
            const int pix = nt * 8 + 2 * r;
            float v0 = acc[mt][nt][0] + tb0, v1 = acc[mt][nt][1] + tb0;
            float v2 = acc[mt][nt][2] + tb1, v3 = acc[mt][nt][3] + tb1;
            *(float2*)&y0[pix] = make_float2(v0 * sigmoidf_(v0), v1 * sigmoidf_(v1));
            *(float2*)&y1[pix] = make_float2(v2 * sigmoidf_(v2), v3 * sigmoidf_(v3));
        }
    }
}

// ---------------------------------------------------------------------------
// Kernel 2: per-(b,c) global sum/max + 4x4 local pool sums (static bins)
// ---------------------------------------------------------------------------
__global__ __launch_bounds__(160) void pool_kernel() {
    const int bc = blockIdx.x;
    const float4* plane = (const float4*)(g_xal + (size_t)bc * NHW);
    const int t = threadIdx.x, wb = t & 3, hr = t >> 2;

    float cell[4];
    float gmx = -1e30f;
    #pragma unroll
    for (int gy = 0; gy < 4; gy++) {
        const float4* rp = plane + ((gy * 40 + hr) * NW + wb * 40) / 4;
        float s = 0.f;
        #pragma unroll
        for (int i = 0; i < 10; i++) {
            float4 v = rp[i];
            s += (v.x + v.y) + (v.z + v.w);
            gmx = fmaxf(gmx, fmaxf(fmaxf(v.x, v.y), fmaxf(v.z, v.w)));
        }
        cell[gy] = s;
    }
    float gs = (cell[0] + cell[1]) + (cell[2] + cell[3]);

    #pragma unroll
    for (int o = 4; o <= 16; o <<= 1)
        #pragma unroll
        for (int gy = 0; gy < 4; gy++)
            cell[gy] += __shfl_xor_sync(0xffffffffu, cell[gy], o);
    #pragma unroll
    for (int o = 1; o <= 16; o <<= 1) {
        gs += __shfl_xor_sync(0xffffffffu, gs, o);
        gmx = fmaxf(gmx, __shfl_xor_sync(0xffffffffu, gmx, o));
    }

    __shared__ float sC[5][4][4], sS[5], sM[5];
    const int w = t >> 5, lanei = t & 31;
    if (lanei < 4) {
        #pragma unroll
        for (int gy = 0; gy < 4; gy++) sC[w][gy][lanei] = cell[gy];
    }
    if (lanei == 0) { sS[w] = gs; sM[w] = gmx; }
    __syncthreads();
    if (t < 16) {
        float v = 0.f;
        #pragma unroll
        for (int w2 = 0; w2 < 5; w2++) v += sC[w2][t >> 2][t & 3];
        g_lsum[bc * 16 + t] = v;
    }
    if (t == 0) {
        float S = 0.f, M = -1e30f;
        #pragma unroll
        for (int w2 = 0; w2 < 5; w2++) { S += sS[w2]; M = fmaxf(M, sM[w2]); }
        g_gsum[bc] = S;
        g_gmax[bc] = M;
    }
}

// ---------------------------------------------------------------------------
// Kernel 3: pre-average offset conv2 weights over the 49 output taps
// ---------------------------------------------------------------------------
__global__ void prep_kernel(const float* __restrict__ off_w2,
                            const float* __restrict__ off_b2) {
    const int i = threadIdx.x;
    if (i < 288) {
        const int d = i / 144, rest = i % 144;
        float s = 0.f;
        for (int j = 0; j < 49; j++) s += off_w2[(d * 49 + j) * 144 + rest];
        g_wavg[i] = s * (1.f / 49.f);
    }
    if (i < 2) {
        float s = 0.f;
        for (int j = 0; j < 49; j++) s += off_b2[i * 49 + j];
        g_bavg[i] = s * (1.f / 49.f);
    }
}

// ---------------------------------------------------------------------------
// Kernel 4: channel attention -> g_ca
// ---------------------------------------------------------------------------
__global__ __launch_bounds__(256) void ca_kernel(
    const float* __restrict__ mlp_w1, const float* __restrict__ mlp_w2,
    const float* __restrict__ loc_w1, const float* __restrict__ loc_w2,
    const float* __restrict__ fusion_w)
{
    const int b = blockIdx.x, tid = threadIdx.x;
    __shared__ float avg[256], mxv[256];
    __shared__ float h1[32], hpart[32][8], hcell[16][16], hbar[16];

    avg[tid] = g_gsum[b * NC + tid] * (1.f / (float)NHW);
    mxv[tid] = g_gmax[b * NC + tid];
    __syncthreads();

    {
        const int m = tid >> 3, part = tid & 7;
        const int mm = m & 15;
        const float* src = (m < 16) ? avg : mxv;
        float a = 0.f;
        #pragma unroll 8
        for (int c = part * 32; c < part * 32 + 32; c++)
            a += mlp_w1[mm * NC + c] * src[c];
        hpart[m][part] = a;
    }
    {
        const int cell = tid >> 4, m2 = tid & 15;
        float a = 0.f;
        #pragma unroll 8
        for (int c = 0; c < NC; c++)
            a += loc_w1[m2 * NC + c] * g_lsum[(b * NC + c) * 16 + cell];
        hcell[cell][m2] = fmaxf(a * (1.f / 1600.f), 0.f);
    }
    __syncthreads();
    if (tid < 32) {
        float a = 0.f;
        #pragma unroll
        for (int p = 0; p < 8; p++) a += hpart[tid][p];
        h1[tid] = fmaxf(a, 0.f);
    }
    if (tid >= 32 && tid < 48) {
        float s = 0.f;
        #pragma unroll
        for (int cell = 0; cell < 16; cell++) s += hcell[cell][tid - 32];
        hbar[tid - 32] = s * (1.f / 16.f);
    }
    __syncthreads();

    float ga = 0.f, la = 0.f;
    #pragma unroll
    for (int m = 0; m < 16; m++) {
        ga += mlp_w2[tid * 16 + m] * (h1[m] + h1[16 + m]);
        la += loc_w2[tid * 16 + m] * hbar[m];
    }
    const float alpha = sigmoidf_(fusion_w[0]);
    g_ca[b * NC + tid] = sigmoidf_(alpha * ga + (1.f - alpha) * la);
}

// ---------------------------------------------------------------------------
// Kernel 5: sf = [mean_c(ca*x), max_c(ca*x)]  (float4)
// ---------------------------------------------------------------------------
__global__ __launch_bounds__(256) void sf_kernel() {
    const int b = blockIdx.y;
    const int p4 = blockIdx.x * 256 + threadIdx.x;
    const float4* xb = (const float4*)(g_xal + (size_t)b * NC * NHW);
    const float* cab = g_ca + b * NC;
    float4 s = make_float4(0.f, 0.f, 0.f, 0.f);
    float4 mx = make_float4(-1e30f, -1e30f, -1e30f, -1e30f);
    #pragma unroll 4
    for (int c = 0; c < NC; c++) {
        const float cc = cab[c];
        float4 v = xb[(size_t)c * (NHW / 4) + p4];
        v.x *= cc; v.y *= cc; v.z *= cc; v.w *= cc;
        s.x += v.x; s.y += v.y; s.z += v.z; s.w += v.w;
        mx.x = fmaxf(mx.x, v.x); mx.y = fmaxf(mx.y, v.y);
        mx.z = fmaxf(mx.z, v.z); mx.w = fmaxf(mx.w, v.w);
    }
    const float inv = 1.f / (float)NC;
    s.x *= inv; s.y *= inv; s.z *= inv; s.w *= inv;
    ((float4*)(g_sf + (size_t)b * 2 * NHW))[p4] = s;
    ((float4*)(g_sf + (size_t)b * 2 * NHW + NHW))[p4] = mx;
}

// ---------------------------------------------------------------------------
// Kernel 6: offset conv1: 3x3, 2->16 + BN + ReLU
// ---------------------------------------------------------------------------
__global__ __launch_bounds__(256) void off1_kernel(
    const float* __restrict__ w1, const float* __restrict__ gg,
    const float* __restrict__ bt, const float* __restrict__ mm,
    const float* __restrict__ vv)
{
    const int p = blockIdx.x * blockDim.x + threadIdx.x;
    const int co = blockIdx.y, b = blockIdx.z;
    const int h = p / NW, w = p % NW;
    const float* sfb = g_sf + (size_t)b * 2 * NHW;
    float acc = 0.f;
    #pragma unroll
    for (int ci = 0; ci < 2; ci++) {
        #pragma unroll
        for (int ky = 0; ky < 3; ky++) {
            const int hy = h + ky - 1;
            if (hy < 0 || hy >= NH) continue;
            #pragma unroll
            for (int kx = 0; kx < 3; kx++) {
                const int wx = w + kx - 1;
                if (wx < 0 || wx >= NW) continue;
                acc += w1[((co * 2 + ci) * 3 + ky) * 3 + kx] *
                       sfb[ci * NHW + hy * NW + wx];
            }
        }
    }
    const float sc = gg[co] * rsqrtf(vv[co] + BN_EPS);
    const float tb = bt[co] - mm[co] * sc;
    g_o1[((size_t)b * 16 + co) * NHW + p] = fmaxf(acc * sc + tb, 0.f);
}

// ---------------------------------------------------------------------------
// Kernel 7: averaged offset conv2 + tanh*0.5 + grid + bilinear sample
// ---------------------------------------------------------------------------
__global__ __launch_bounds__(256) void off2_sample_kernel() {
    const int b = blockIdx.y;
    const int p = blockIdx.x * blockDim.x + threadIdx.x;
    const int h = p / NW, w = p % NW;
    const float* o1b = g_o1 + (size_t)b * 16 * NHW;

    float off[2];
    #pragma unroll
    for (int d = 0; d < 2; d++) {
        float acc = g_bavg[d];
        for (int ci = 0; ci < 16; ci++) {
            #pragma unroll
            for (int ky = 0; ky < 3; ky++) {
                const int hy = h + ky - 1;
                if (hy < 0 || hy >= NH) continue;
                #pragma unroll
                for (int kx = 0; kx < 3; kx++) {
                    const int wx = w + kx - 1;
                    if (wx < 0 || wx >= NW) continue;
                    acc += g_wavg[(d * 16 + ci) * 9 + ky * 3 + kx] *
                           o1b[(size_t)ci * NHW + hy * NW + wx];
                }
            }
        }
        off[d] = tanhf(acc) * 0.5f;
    }

    const float bx = -1.f + 2.f * (float)w / 159.f;
    const float by = -1.f + 2.f * (float)h / 159.f;
    const float gx = fminf(fmaxf(bx + off[0], -1.f), 1.f);
    const float gy = fminf(fmaxf(by + off[1], -1.f), 1.f);

    const float fx = (gx + 1.f) * ((float)NW * 0.5f) - 0.5f;
    const float fy = (gy + 1.f) * ((float)NH * 0.5f) - 0.5f;
    const float x0f = floorf(fx), y0f = floorf(fy);
    const int x0 = (int)x0f, y0 = (int)y0f;
    const float wx = fx - x0f, wy = fy - y0f;

    const float* sfb = g_sf + (size_t)b * 2 * NHW;
    float out0 = 0.f, out1 = 0.f;
    #pragma unroll
    for (int dy = 0; dy < 2; dy++) {
        const int yy = y0 + dy;
        if (yy < 0 || yy >= NH) continue;
        const float wgy = dy ? wy : (1.f - wy);
        #pragma unroll
        for (int dx = 0; dx < 2; dx++) {
            const int xx = x0 + dx;
            if (xx < 0 || xx >= NW) continue;
            const float wt = wgy * (dx ? wx : (1.f - wx));
            out0 += wt * sfb[yy * NW + xx];
            out1 += wt * sfb[NHW + yy * NW + xx];
        }
    }
    g_sampled[(size_t)b * 2 * NHW + p] = out0;
    g_sampled[(size_t)b * 2 * NHW + NHW + p] = out1;
}

// ---------------------------------------------------------------------------
// Kernel 8: 7x7 conv (2->1) over sampled + sigmoid -> g_sa
// ---------------------------------------------------------------------------
__global__ __launch_bounds__(256) void sa_kernel(const float* __restrict__ attn_w) {
    const int b = blockIdx.y;
    const int p = blockIdx.x * blockDim.x + threadIdx.x;
    const int h = p / NW, w = p % NW;
    const float* sm = g_sampled + (size_t)b * 2 * NHW;
    float acc = 0.f;
    #pragma unroll
    for (int ci = 0; ci < 2; ci++) {
        #pragma unroll
        for (int ky = 0; ky < 7; ky++) {
            const int hy = h + ky - 3;
            if (hy < 0 || hy >= NH) continue;
            #pragma unroll
            for (int kx = 0; kx < 7; kx++) {
                const int wx = w + kx - 3;
                if (wx < 0 || wx >= NW) continue;
                acc += attn_w[(ci * 7 + ky) * 7 + kx] *
                       sm[ci * NHW + hy * NW + wx];
            }
        }
    }
    g_sa[b * NHW + p] = sigmoidf_(acc);
}

// ---------------------------------------------------------------------------
// Kernel 9: out = sa * ca * x_aligned
// ---------------------------------------------------------------------------
__global__ __launch_bounds__(256) void final_kernel(float* __restrict__ out) {
    const unsigned idx4 = blockIdx.x * blockDim.x + threadIdx.x;
    const unsigned total4 = (unsigned)NB * NC * NHW / 4;
    if (idx4 >= total4) return;
    const unsigned e = idx4 * 4;
    const unsigned p = e % NHW;
    const unsigned c = (e / NHW) % NC;
    const unsigned b = e / (NHW * NC);
    const float4 xv = *reinterpret_cast<const float4*>(&g_xal[e]);
    const float4 sav = *reinterpret_cast<const float4*>(&g_sa[b * NHW + p]);
    const float cc = g_ca[b * NC + c];
    float4 r;
    r.x = xv.x * sav.x * cc;
    r.y = xv.y * sav.y * cc;
    r.z = xv.z * sav.z * cc;
    r.w = xv.w * sav.w * cc;
    *reinterpret_cast<float4*>(&out[e]) = r;
}

// ---------------------------------------------------------------------------
extern "C" void kernel_launch(void* const* d_in, const int* in_sizes, int n_in,
                              void* d_out, int out_size) {
    const float* x       = (const float*)d_in[0];
    const float* align_w = (const float*)d_in[1];
    const float* align_g = (const float*)d_in[2];
    const float* align_b = (const float*)d_in[3];
    const float* align_m = (const float*)d_in[4];
    const float* align_v = (const float*)d_in[5];
    const float* mlp_w1  = (const float*)d_in[6];
    const float* mlp_w2  = (const float*)d_in[7];
    const float* loc_w1  = (const float*)d_in[8];
    const float* loc_w2  = (const float*)d_in[9];
    const float* fusion  = (const float*)d_in[10];
    const float* off_w1  = (const float*)d_in[11];
    const float* off_g   = (const float*)d_in[12];
    const float* off_bt  = (const float*)d_in[13];
    const float* off_m   = (const float*)d_in[14];
    const float* off_v   = (const float*)d_in[15];
    const float* off_w2  = (const float*)d_in[16];
    const float* off_b2  = (const float*)d_in[17];
    const float* attn_w  = (const float*)d_in[18];
    float* out = (float*)d_out;

    static bool attrSet = false;
    if (!attrSet) {
        cudaFuncSetAttribute(gemm_kernel,
                             cudaFuncAttributeMaxDynamicSharedMemorySize,
                             DSMEM_U32 * 4);
        attrSet = true;
    }

    wpack_kernel<<<128, 256>>>(align_w, align_g, align_b, align_m, align_v);
    prep_kernel<<<1, 288>>>(off_w2, off_b2);

    dim3 gGemm(NTILES, NB);
    gemm_kernel<<<gGemm, 256, DSMEM_U32 * 4>>>(x);

    pool_kernel<<<NB * NC, 160>>>();
    ca_kernel<<<NB, 256>>>(mlp_w1, mlp_w2, loc_w1, loc_w2, fusion);

    dim3 gPix4(NHW / 4 / 256, NB);
    sf_kernel<<<gPix4, 256>>>();

    dim3 gPix(NHW / 256, NB);
    dim3 gOff1(NHW / 256, 16, NB);
    off1_kernel<<<gOff1, 256>>>(off_w1, off_g, off_bt, off_m, off_v);
    off2_sample_kernel<<<gPix, 256>>>();
    sa_kernel<<<gPix, 256>>>(attn_w);

    const unsigned total4 = (unsigned)NB * NC * NHW / 4;
    final_kernel<<<(total4 + 255) / 256, 256>>>(out);
}

// round 11
// speedup vs baseline: 2.1626x; 1.0847x over previous
#include <cuda_runtime.h>
#include <cuda_fp16.h>
#include <cstdint>

static constexpr int NB = 8;
static constexpr int NC = 256;
static constexpr int NH = 160;
static constexpr int NW = 160;
static constexpr int NHW = NH * NW;           // 25600
static constexpr int TILE_N = 64;
static constexpr int NTILES = NHW / TILE_N;   // 400
static constexpr float BN_EPS = 1e-5f;

// dynamic smem (u32 units):
//   W stages: 2 x 10240 (each = 2 subs of 5120)   at 0
//   X stages: 2 x 2560  (each = 2 subs of 1280)   at 20480
static constexpr int SM_X = 20480;
static constexpr int DSMEM_U32 = 25600;       // 100 KB

// ---------------- scratch (static device globals) --------------------------
__device__ __half g_xalh[(size_t)NB * NC * NHW];   // fp16 aligned activations
__device__ uint32_t g_wph[NC * 128];     // packed fp16x2 (k-pairs) BN-scaled W
__device__ float g_bias[NC];
__device__ float g_gsum[NB * NC];
__device__ float g_gmax[NB * NC];
__device__ float g_lsum[NB * NC * 16];
__device__ float g_ca[NB * NC];
__device__ float g_sf[NB * 2 * NHW];
__device__ float g_o1[NB * 16 * NHW];
__device__ float g_sampled[NB * 2 * NHW];
__device__ float g_sa[NB * NHW];
__device__ float g_wavg[2 * 16 * 9];
__device__ float g_bavg[2];

__device__ __forceinline__ float sigmoidf_(float x) {
    return 1.f / (1.f + __expf(-x));
}
__device__ __forceinline__ uint32_t packh(__half a, __half b) {
    __half2 t = __halves2half2(a, b);     // low = a
    return *reinterpret_cast<uint32_t*>(&t);
}
__device__ __forceinline__ float2 h2f2(uint32_t u) {
    return __half22float2(*reinterpret_cast<__half2*>(&u));
}
__device__ __forceinline__ void mma16816h(float* c, const uint32_t* a,
                                          uint32_t b0, uint32_t b1) {
    asm volatile(
        "mma.sync.aligned.m16n8k16.row.col.f32.f16.f16.f32 "
        "{%0,%1,%2,%3}, {%4,%5,%6,%7}, {%8,%9}, {%0,%1,%2,%3};"
        : "+f"(c[0]), "+f"(c[1]), "+f"(c[2]), "+f"(c[3])
        : "r"(a[0]), "r"(a[1]), "r"(a[2]), "r"(a[3]), "r"(b0), "r"(b1));
}
__device__ __forceinline__ void ldsm4(uint32_t* d, uint32_t addr) {
    asm volatile(
        "ldmatrix.sync.aligned.m8n8.x4.shared.b16 {%0,%1,%2,%3}, [%4];"
        : "=r"(d[0]), "=r"(d[1]), "=r"(d[2]), "=r"(d[3]) : "r"(addr));
}

// ---------------------------------------------------------------------------
// Kernel 0: pack BN-scaled weights into fp16 k-pairs
// ---------------------------------------------------------------------------
__global__ __launch_bounds__(256) void wpack_kernel(
    const float* __restrict__ w, const float* __restrict__ g,
    const float* __restrict__ bb, const float* __restrict__ m,
    const float* __restrict__ v)
{
    const int id = blockIdx.x * 256 + threadIdx.x;   // 0..32767
    const int co = id >> 7, kp = id & 127;
    const float sc = g[co] * rsqrtf(v[co] + BN_EPS);
    const float w0 = w[co * 256 + 2 * kp] * sc;
    const float w1 = w[co * 256 + 2 * kp + 1] * sc;
    g_wph[co * 128 + kp] = packh(__float2half_rn(w0), __float2half_rn(w1));
    if (kp == 0) g_bias[co] = bb[co] - m[co] * sc;
}

// ---------------------------------------------------------------------------
// Kernel 1: tensor-core GEMM, CTA = [256 co x 64 px], K=256 in 4 chunks of 64.
//   fp16 single pass, occ 2, double-buffered, one sync pair per chunk.
//   Epilogue: bias + SiLU -> fp16 store.
// ---------------------------------------------------------------------------
__global__ void __launch_bounds__(256, 2) gemm_kernel(const float* __restrict__ X)
{
    extern __shared__ uint32_t sm[];
    const int tile = blockIdx.x, b = blockIdx.y;
    const int tileBase = tile * TILE_N;
    const int t = threadIdx.x, lane = t & 31, warp = t >> 5;   // warp = warpM 0..7
    const int q = lane >> 2, r = lane & 3;
    const float* Xb = X + (size_t)b * NC * NHW + tileBase;
    const int kq = t & 31, pg = t >> 5;       // X staging: kpair 0..31, px grp 0..7

    const uint32_t smBase = (uint32_t)__cvta_generic_to_shared(sm);
    const uint32_t aOff = (uint32_t)((warp * 32 + (lane & 15)) * 20 + ((lane >> 4) << 2));
    const uint32_t bOff = (uint32_t)((((lane & 16) ? 8 : 0) + (lane & 7)) * 20
                                     + ((lane & 8) ? 4 : 0));

    float acc[2][8][4];
    #pragma unroll
    for (int i = 0; i < 2; i++)
        #pragma unroll
        for (int j = 0; j < 8; j++)
            #pragma unroll
            for (int k = 0; k < 4; k++) acc[i][j][k] = 0.f;

    float4 xr0, xr1, xr2, xr3;

    auto cpW = [&](int c, int s) {
        const uint32_t dW = smBase + (uint32_t)(s * 10240) * 4u;
        #pragma unroll
        for (int i = 0; i < 8; i++) {
            const int L = i * 256 + t;                 // 0..2047 16B lines
            const int sub = L >> 10, lid = L & 1023;
            const int row = lid >> 2, grp = lid & 3;
            const uint32_t off = (uint32_t)(sub * 5120 + row * 20 + grp * 4) * 4u;
            const uint32_t* s1 = &g_wph[row * 128 + c * 32 + sub * 16 + grp * 4];
            asm volatile("cp.async.cg.shared.global [%0], [%1], 16;"
                         :: "r"(dW + off), "l"(s1));
        }
        asm volatile("cp.async.commit_group;");
    };
    auto ldgX = [&](int c) {
        const float* x0 = Xb + (size_t)(c * 64 + 2 * kq) * NHW + pg * 8;
        xr0 = *(const float4*)x0;       xr1 = *(const float4*)(x0 + 4);
        xr2 = *(const float4*)(x0 + NHW); xr3 = *(const float4*)(x0 + NHW + 4);
    };
    auto stsX = [&](int sx) {
        float e0[8] = {xr0.x, xr0.y, xr0.z, xr0.w, xr1.x, xr1.y, xr1.z, xr1.w};
        float e1[8] = {xr2.x, xr2.y, xr2.z, xr2.w, xr3.x, xr3.y, xr3.z, xr3.w};
        const int base = SM_X + sx * 2560 + (kq >> 4) * 1280;
        const int kpc = kq & 15;
        #pragma unroll
        for (int j = 0; j < 8; j++) {
            sm[base + (pg * 8 + j) * 20 + kpc] =
                packh(__float2half_rn(e0[j]), __float2half_rn(e1[j]));
        }
    };

    // ---- prologue ----
    cpW(0, 0);
    ldgX(0);
    stsX(0);
    ldgX(1);
    asm volatile("cp.async.wait_group 0;");
    __syncthreads();

    for (int c = 0; c < 4; c++) {
        if (c < 3) {
            stsX((c + 1) & 1);          // from regs of X(c+1)
            cpW(c + 1, (c + 1) & 1);
        }
        if (c < 2) ldgX(c + 2);

        const uint32_t whB = smBase + (uint32_t)((c & 1) * 10240) * 4u;
        const uint32_t xhB = smBase + (uint32_t)(SM_X + (c & 1) * 2560) * 4u;

        #pragma unroll
        for (int sub = 0; sub < 2; sub++) {
            const uint32_t whS = whB + (uint32_t)(sub * 5120) * 4u;
            const uint32_t xhS = xhB + (uint32_t)(sub * 1280) * 4u;
            #pragma unroll
            for (int ks = 0; ks < 2; ks++) {
                uint32_t Ah[2][4];
                #pragma unroll
                for (int mt = 0; mt < 2; mt++)
                    ldsm4(Ah[mt], whS + (aOff + mt * 320 + ks * 8) * 4u);
                #pragma unroll
                for (int np = 0; np < 4; np++) {
                    uint32_t B0[4];
                    ldsm4(B0, xhS + (bOff + np * 320 + ks * 8) * 4u);
                    #pragma unroll
                    for (int j = 0; j < 2; j++)
                        #pragma unroll
                        for (int mt = 0; mt < 2; mt++)
                            mma16816h(acc[mt][np * 2 + j], Ah[mt],
                                      B0[2 * j], B0[2 * j + 1]);
                }
            }
        }
        if (c < 3) asm volatile("cp.async.wait_group 0;");
        __syncthreads();
    }

    // ---- epilogue: bias + SiLU + fp16 store ----
    #pragma unroll
    for (int mt = 0; mt < 2; mt++) {
        const int co0 = warp * 32 + mt * 16 + q;
        const int co1 = co0 + 8;
        const float tb0 = g_bias[co0], tb1 = g_bias[co1];
        __half* y0 = g_xalh + ((size_t)b * NC + co0) * NHW + tileBase;
        __half* y1 = g_xalh + ((size_t)b * NC + co1) * NHW + tileBase;
        #pragma unroll
        for (int nt = 0; nt < 8; nt++) {
            const int pix = nt * 8 + 2 * r;
            float v0 = acc[mt][nt][0] + tb0, v1 = acc[mt][nt][1] + tb0;
            float v2 = acc[mt][nt][2] + tb1, v3 = acc[mt][nt][3] + tb1;
            *(__half2*)&y0[pix] =
                __floats2half2_rn(v0 * sigmoidf_(v0), v1 * sigmoidf_(v1));
            *(__half2*)&y1[pix] =
                __floats2half2_rn(v2 * sigmoidf_(v2), v3 * sigmoidf_(v3));
        }
    }
}

// ---------------------------------------------------------------------------
// Kernel 2: per-(b,c) global sum/max + 4x4 local pool sums (fp16 input)
// ---------------------------------------------------------------------------
__global__ __launch_bounds__(160) void pool_kernel() {
    const int bc = blockIdx.x;
    const __half* plane = g_xalh + (size_t)bc * NHW;
    const int t = threadIdx.x, wb = t & 3, hr = t >> 2;

    float cell[4];
    float gmx = -1e30f;
    #pragma unroll
    for (int gy = 0; gy < 4; gy++) {
        const uint4* rp = (const uint4*)(plane + (gy * 40 + hr) * NW + wb * 40);
        float s = 0.f;
        #pragma unroll
        for (int i = 0; i < 5; i++) {           // 5 x 8 halves = 40
            uint4 v = rp[i];
            float2 f0 = h2f2(v.x), f1 = h2f2(v.y), f2 = h2f2(v.z), f3 = h2f2(v.w);
            s += (f0.x + f0.y) + (f1.x + f1.y) + (f2.x + f2.y) + (f3.x + f3.y);
            gmx = fmaxf(gmx, fmaxf(fmaxf(fmaxf(f0.x, f0.y), fmaxf(f1.x, f1.y)),
                                   fmaxf(fmaxf(f2.x, f2.y), fmaxf(f3.x, f3.y))));
        }
        cell[gy] = s;
    }
    float gs = (cell[0] + cell[1]) + (cell[2] + cell[3]);

    #pragma unroll
    for (int o = 4; o <= 16; o <<= 1)
        #pragma unroll
        for (int gy = 0; gy < 4; gy++)
            cell[gy] += __shfl_xor_sync(0xffffffffu, cell[gy], o);
    #pragma unroll
    for (int o = 1; o <= 16; o <<= 1) {
        gs += __shfl_xor_sync(0xffffffffu, gs, o);
        gmx = fmaxf(gmx, __shfl_xor_sync(0xffffffffu, gmx, o));
    }

    __shared__ float sC[5][4][4], sS[5], sM[5];
    const int w = t >> 5, lanei = t & 31;
    if (lanei < 4) {
        #pragma unroll
        for (int gy = 0; gy < 4; gy++) sC[w][gy][lanei] = cell[gy];
    }
    if (lanei == 0) { sS[w] = gs; sM[w] = gmx; }
    __syncthreads();
    if (t < 16) {
        float v = 0.f;
        #pragma unroll
        for (int w2 = 0; w2 < 5; w2++) v += sC[w2][t >> 2][t & 3];
        g_lsum[bc * 16 + t] = v;
    }
    if (t == 0) {
        float S = 0.f, M = -1e30f;
        #pragma unroll
        for (int w2 = 0; w2 < 5; w2++) { S += sS[w2]; M = fmaxf(M, sM[w2]); }
        g_gsum[bc] = S;
        g_gmax[bc] = M;
    }
}

// ---------------------------------------------------------------------------
// Kernel 3: pre-average offset conv2 weights over the 49 output taps
// ---------------------------------------------------------------------------
__global__ void prep_kernel(const float* __restrict__ off_w2,
                            const float* __restrict__ off_b2) {
    const int i = threadIdx.x;
    if (i < 288) {
        const int d = i / 144, rest = i % 144;
        float s = 0.f;
        for (int j = 0; j < 49; j++) s += off_w2[(d * 49 + j) * 144 + rest];
        g_wavg[i] = s * (1.f / 49.f);
    }
    if (i < 2) {
        float s = 0.f;
        for (int j = 0; j < 49; j++) s += off_b2[i * 49 + j];
        g_bavg[i] = s * (1.f / 49.f);
    }
}

// ---------------------------------------------------------------------------
// Kernel 4: channel attention -> g_ca
// ---------------------------------------------------------------------------
__global__ __launch_bounds__(256) void ca_kernel(
    const float* __restrict__ mlp_w1, const float* __restrict__ mlp_w2,
    const float* __restrict__ loc_w1, const float* __restrict__ loc_w2,
    const float* __restrict__ fusion_w)
{
    const int b = blockIdx.x, tid = threadIdx.x;
    __shared__ float avg[256], mxv[256];
    __shared__ float h1[32], hpart[32][8], hcell[16][16], hbar[16];

    avg[tid] = g_gsum[b * NC + tid] * (1.f / (float)NHW);
    mxv[tid] = g_gmax[b * NC + tid];
    __syncthreads();

    {
        const int m = tid >> 3, part = tid & 7;
        const int mm = m & 15;
        const float* src = (m < 16) ? avg : mxv;
        float a = 0.f;
        #pragma unroll 8
        for (int c = part * 32; c < part * 32 + 32; c++)
            a += mlp_w1[mm * NC + c] * src[c];
        hpart[m][part] = a;
    }
    {
        const int cell = tid >> 4, m2 = tid & 15;
        float a = 0.f;
        #pragma unroll 8
        for (int c = 0; c < NC; c++)
            a += loc_w1[m2 * NC + c] * g_lsum[(b * NC + c) * 16 + cell];
        hcell[cell][m2] = fmaxf(a * (1.f / 1600.f), 0.f);
    }
    __syncthreads();
    if (tid < 32) {
        float a = 0.f;
        #pragma unroll
        for (int p = 0; p < 8; p++) a += hpart[tid][p];
        h1[tid] = fmaxf(a, 0.f);
    }
    if (tid >= 32 && tid < 48) {
        float s = 0.f;
        #pragma unroll
        for (int cell = 0; cell < 16; cell++) s += hcell[cell][tid - 32];
        hbar[tid - 32] = s * (1.f / 16.f);
    }
    __syncthreads();

    float ga = 0.f, la = 0.f;
    #pragma unroll
    for (int m = 0; m < 16; m++) {
        ga += mlp_w2[tid * 16 + m] * (h1[m] + h1[16 + m]);
        la += loc_w2[tid * 16 + m] * hbar[m];
    }
    const float alpha = sigmoidf_(fusion_w[0]);
    g_ca[b * NC + tid] = sigmoidf_(alpha * ga + (1.f - alpha) * la);
}

// ---------------------------------------------------------------------------
// Kernel 5: sf = [mean_c(ca*x), max_c(ca*x)]  (fp16 input, 4 px / thread)
// ---------------------------------------------------------------------------
__global__ __launch_bounds__(256) void sf_kernel() {
    const int b = blockIdx.y;
    const int p4 = blockIdx.x * 256 + threadIdx.x;       // 0..6399
    const __half* xb = g_xalh + (size_t)b * NC * NHW;
    const float* cab = g_ca + b * NC;
    float4 s = make_float4(0.f, 0.f, 0.f, 0.f);
    float4 mx = make_float4(-1e30f, -1e30f, -1e30f, -1e30f);
    #pragma unroll 4
    for (int c = 0; c < NC; c++) {
        const float cc = cab[c];
        uint2 u = *(const uint2*)(xb + (size_t)c * NHW + p4 * 4);
        float2 f0 = h2f2(u.x), f1 = h2f2(u.y);
        float v0 = cc * f0.x, v1 = cc * f0.y, v2 = cc * f1.x, v3 = cc * f1.y;
        s.x += v0; s.y += v1; s.z += v2; s.w += v3;
        mx.x = fmaxf(mx.x, v0); mx.y = fmaxf(mx.y, v1);
        mx.z = fmaxf(mx.z, v2); mx.w = fmaxf(mx.w, v3);
    }
    const float inv = 1.f / (float)NC;
    s.x *= inv; s.y *= inv; s.z *= inv; s.w *= inv;
    ((float4*)(g_sf + (size_t)b * 2 * NHW))[p4] = s;
    ((float4*)(g_sf + (size_t)b * 2 * NHW + NHW))[p4] = mx;
}

// ---------------------------------------------------------------------------
// Kernel 6: offset conv1: 3x3, 2->16 + BN + ReLU
// ---------------------------------------------------------------------------
__global__ __launch_bounds__(256) void off1_kernel(
    const float* __restrict__ w1, const float* __restrict__ gg,
    const float* __restrict__ bt, const float* __restrict__ mm,
    const float* __restrict__ vv)
{
    const int p = blockIdx.x * blockDim.x + threadIdx.x;
    const int co = blockIdx.y, b = blockIdx.z;
    const int h = p / NW, w = p % NW;
    const float* sfb = g_sf + (size_t)b * 2 * NHW;
    float acc = 0.f;
    #pragma unroll
    for (int ci = 0; ci < 2; ci++) {
        #pragma unroll
        for (int ky = 0; ky < 3; ky++) {
            const int hy = h + ky - 1;
            if (hy < 0 || hy >= NH) continue;
            #pragma unroll
            for (int kx = 0; kx < 3; kx++) {
                const int wx = w + kx - 1;
                if (wx < 0 || wx >= NW) continue;
                acc += w1[((co * 2 + ci) * 3 + ky) * 3 + kx] *
                       sfb[ci * NHW + hy * NW + wx];
            }
        }
    }
    const float sc = gg[co] * rsqrtf(vv[co] + BN_EPS);
    const float tb = bt[co] - mm[co] * sc;
    g_o1[((size_t)b * 16 + co) * NHW + p] = fmaxf(acc * sc + tb, 0.f);
}

// ---------------------------------------------------------------------------
// Kernel 7: averaged offset conv2 + tanh*0.5 + grid + bilinear sample
// ---------------------------------------------------------------------------
__global__ __launch_bounds__(256) void off2_sample_kernel() {
    const int b = blockIdx.y;
    const int p = blockIdx.x * blockDim.x + threadIdx.x;
    const int h = p / NW, w = p % NW;
    const float* o1b = g_o1 + (size_t)b * 16 * NHW;

    float off[2];
    #pragma unroll
    for (int d = 0; d < 2; d++) {
        float acc = g_bavg[d];
        for (int ci = 0; ci < 16; ci++) {
            #pragma unroll
            for (int ky = 0; ky < 3; ky++) {
                const int hy = h + ky - 1;
                if (hy < 0 || hy >= NH) continue;
                #pragma unroll
                for (int kx = 0; kx < 3; kx++) {
                    const int wx = w + kx - 1;
                    if (wx < 0 || wx >= NW) continue;
                    acc += g_wavg[(d * 16 + ci) * 9 + ky * 3 + kx] *
                           o1b[(size_t)ci * NHW + hy * NW + wx];
                }
            }
        }
        off[d] = tanhf(acc) * 0.5f;
    }

    const float bx = -1.f + 2.f * (float)w / 159.f;
    const float by = -1.f + 2.f * (float)h / 159.f;
    const float gx = fminf(fmaxf(bx + off[0], -1.f), 1.f);
    const float gy = fminf(fmaxf(by + off[1], -1.f), 1.f);

    const float fx = (gx + 1.f) * ((float)NW * 0.5f) - 0.5f;
    const float fy = (gy + 1.f) * ((float)NH * 0.5f) - 0.5f;
    const float x0f = floorf(fx), y0f = floorf(fy);
    const int x0 = (int)x0f, y0 = (int)y0f;
    const float wx = fx - x0f, wy = fy - y0f;

    const float* sfb = g_sf + (size_t)b * 2 * NHW;
    float out0 = 0.f, out1 = 0.f;
    #pragma unroll
    for (int dy = 0; dy < 2; dy++) {
        const int yy = y0 + dy;
        if (yy < 0 || yy >= NH) continue;
        const float wgy = dy ? wy : (1.f - wy);
        #pragma unroll
        for (int dx = 0; dx < 2; dx++) {
            const int xx = x0 + dx;
            if (xx < 0 || xx >= NW) continue;
            const float wt = wgy * (dx ? wx : (1.f - wx));
            out0 += wt * sfb[yy * NW + xx];
            out1 += wt * sfb[NHW + yy * NW + xx];
        }
    }
    g_sampled[(size_t)b * 2 * NHW + p] = out0;
    g_sampled[(size_t)b * 2 * NHW + NHW + p] = out1;
}

// ---------------------------------------------------------------------------
// Kernel 8: 7x7 conv (2->1) over sampled + sigmoid -> g_sa
// ---------------------------------------------------------------------------
__global__ __launch_bounds__(256) void sa_kernel(const float* __restrict__ attn_w) {
    const int b = blockIdx.y;
    const int p = blockIdx.x * blockDim.x + threadIdx.x;
    const int h = p / NW, w = p % NW;
    const float* sm = g_sampled + (size_t)b * 2 * NHW;
    float acc = 0.f;
    #pragma unroll
    for (int ci = 0; ci < 2; ci++) {
        #pragma unroll
        for (int ky = 0; ky < 7; ky++) {
            const int hy = h + ky - 3;
            if (hy < 0 || hy >= NH) continue;
            #pragma unroll
            for (int kx = 0; kx < 7; kx++) {
                const int wx = w + kx - 3;
                if (wx < 0 || wx >= NW) continue;
                acc += attn_w[(ci * 7 + ky) * 7 + kx] *
                       sm[ci * NHW + hy * NW + wx];
            }
        }
    }
    g_sa[b * NHW + p] = sigmoidf_(acc);
}

// ---------------------------------------------------------------------------
// Kernel 9: out = sa * ca * x_aligned  (fp16 xal, 4 elems / thread)
// ---------------------------------------------------------------------------
__global__ __launch_bounds__(256) void final_kernel(float* __restrict__ out) {
    const unsigned idx4 = blockIdx.x * blockDim.x + threadIdx.x;
    const unsigned total4 = (unsigned)NB * NC * NHW / 4;
    if (idx4 >= total4) return;
    const unsigned e = idx4 * 4;
    const unsigned p = e % NHW;
    const unsigned c = (e / NHW) % NC;
    const unsigned b = e / (NHW * NC);
    uint2 u = *(const uint2*)(g_xalh + e);
    float2 f0 = h2f2(u.x), f1 = h2f2(u.y);
    const float4 sav = *reinterpret_cast<const float4*>(&g_sa[b * NHW + p]);
    const float cc = g_ca[b * NC + c];
    float4 r;
    r.x = f0.x * sav.x * cc;
    r.y = f0.y * sav.y * cc;
    r.z = f1.x * sav.z * cc;
    r.w = f1.y * sav.w * cc;
    *reinterpret_cast<float4*>(&out[e]) = r;
}

// ---------------------------------------------------------------------------
extern "C" void kernel_launch(void* const* d_in, const int* in_sizes, int n_in,
                              void* d_out, int out_size) {
    const float* x       = (const float*)d_in[0];
    const float* align_w = (const float*)d_in[1];
    const float* align_g = (const float*)d_in[2];
    const float* align_b = (const float*)d_in[3];
    const float* align_m = (const float*)d_in[4];
    const float* align_v = (const float*)d_in[5];
    const float* mlp_w1  = (const float*)d_in[6];
    const float* mlp_w2  = (const float*)d_in[7];
    const float* loc_w1  = (const float*)d_in[8];
    const float* loc_w2  = (const float*)d_in[9];
    const float* fusion  = (const float*)d_in[10];
    const float* off_w1  = (const float*)d_in[11];
    const float* off_g   = (const float*)d_in[12];
    const float* off_bt  = (const float*)d_in[13];
    const float* off_m   = (const float*)d_in[14];
    const float* off_v   = (const float*)d_in[15];
    const float* off_w2  = (const float*)d_in[16];
    const float* off_b2  = (const float*)d_in[17];
    const float* attn_w  = (const float*)d_in[18];
    float* out = (float*)d_out;

    static bool attrSet = false;
    if (!attrSet) {
        cudaFuncSetAttribute(gemm_kernel,
                             cudaFuncAttributeMaxDynamicSharedMemorySize,
                             DSMEM_U32 * 4);
        attrSet = true;
    }

    wpack_kernel<<<128, 256>>>(align_w, align_g, align_b, align_m, align_v);
    prep_kernel<<<1, 288>>>(off_w2, off_b2);

    dim3 gGemm(NTILES, NB);
    gemm_kernel<<<gGemm, 256, DSMEM_U32 * 4>>>(x);

    pool_kernel<<<NB * NC, 160>>>();
    ca_kernel<<<NB, 256>>>(mlp_w1, mlp_w2, loc_w1, loc_w2, fusion);

    dim3 gPix4(NHW / 4 / 256, NB);
    sf_kernel<<<gPix4, 256>>>();

    dim3 gPix(NHW / 256, NB);
    dim3 gOff1(NHW / 256, 16, NB);
    off1_kernel<<<gOff1, 256>>>(off_w1, off_g, off_bt, off_m, off_v);
    off2_sample_kernel<<<gPix, 256>>>();
    sa_kernel<<<gPix, 256>>>(attn_w);

    const unsigned total4 = (unsigned)NB * NC * NHW / 4;
    final_kernel<<<(total4 + 255) / 256, 256>>>(out);
}

// round 12
// speedup vs baseline: 2.2458x; 1.0385x over previous
#include <cuda_runtime.h>
#include <cuda_fp16.h>
#include <cstdint>

static constexpr int NB = 8;
static constexpr int NC = 256;
static constexpr int NH = 160;
static constexpr int NW = 160;
static constexpr int NHW = NH * NW;           // 25600
static constexpr int TILE_N = 64;
static constexpr int NTILES = NHW / TILE_N;   // 400
static constexpr float BN_EPS = 1e-5f;

// dynamic smem (u32 units): X double buffer, 2 stages x 2560 (2 subs of 1280)
static constexpr int DSMEM_U32 = 5120;        // 20 KB

// ---------------- scratch (static device globals) --------------------------
__device__ __half g_xalh[(size_t)NB * NC * NHW];   // fp16 aligned activations
__device__ uint32_t g_wfragA[256 * 128];  // W in mma-A-fragment layout (128 KB)
__device__ float g_bias[NC];
__device__ float g_gsum[NB * NC];
__device__ float g_gmax[NB * NC];
__device__ float g_lsum[NB * NC * 16];
__device__ float g_ca[NB * NC];
__device__ float g_sf[NB * 2 * NHW];
__device__ float g_o1[NB * 16 * NHW];
__device__ float g_sampled[NB * 2 * NHW];
__device__ float g_sa[NB * NHW];
__device__ float g_wavg[2 * 16 * 9];
__device__ float g_bavg[2];

__device__ __forceinline__ float sigmoidf_(float x) {
    return 1.f / (1.f + __expf(-x));
}
__device__ __forceinline__ uint32_t packh(__half a, __half b) {
    __half2 t = __halves2half2(a, b);     // low = a
    return *reinterpret_cast<uint32_t*>(&t);
}
__device__ __forceinline__ float2 h2f2(uint32_t u) {
    return __half22float2(*reinterpret_cast<__half2*>(&u));
}
__device__ __forceinline__ void mma16816h(float* c, uint32_t a0, uint32_t a1,
                                          uint32_t a2, uint32_t a3,
                                          uint32_t b0, uint32_t b1) {
    asm volatile(
        "mma.sync.aligned.m16n8k16.row.col.f32.f16.f16.f32 "
        "{%0,%1,%2,%3}, {%4,%5,%6,%7}, {%8,%9}, {%0,%1,%2,%3};"
        : "+f"(c[0]), "+f"(c[1]), "+f"(c[2]), "+f"(c[3])
        : "r"(a0), "r"(a1), "r"(a2), "r"(a3), "r"(b0), "r"(b1));
}
__device__ __forceinline__ void ldsm4(uint32_t* d, uint32_t addr) {
    asm volatile(
        "ldmatrix.sync.aligned.m8n8.x4.shared.b16 {%0,%1,%2,%3}, [%4];"
        : "=r"(d[0]), "=r"(d[1]), "=r"(d[2]), "=r"(d[3]) : "r"(addr));
}

// ---------------------------------------------------------------------------
// Kernel 0: pack BN-scaled weights into fp16 k-pairs in A-FRAGMENT layout.
// Tile (cb, kb): cb = co block of 16, kb = kpair block of 8.
// lane = (m&7)*4 + (kl&3); i = (m>=8) + 2*(kl>=4).
// ---------------------------------------------------------------------------
__global__ __launch_bounds__(256) void wpack_kernel(
    const float* __restrict__ w, const float* __restrict__ g,
    const float* __restrict__ bb, const float* __restrict__ m,
    const float* __restrict__ v)
{
    const int id = blockIdx.x * 256 + threadIdx.x;   // 0..32767
    const int co = id >> 7, kp = id & 127;
    const float sc = g[co] * rsqrtf(v[co] + BN_EPS);
    const float w0 = w[co * 256 + 2 * kp] * sc;
    const float w1 = w[co * 256 + 2 * kp + 1] * sc;
    const uint32_t packed = packh(__float2half_rn(w0), __float2half_rn(w1));

    const int cb = co >> 4, mm = co & 15;
    const int kb = kp >> 3, kl = kp & 7;
    const int lane = (mm & 7) * 4 + (kl & 3);
    const int i = ((mm >> 3) & 1) | (((kl >> 2) & 1) << 1);
    g_wfragA[(((cb * 16) + kb) * 32 + lane) * 4 + i] = packed;
    if (kp == 0) g_bias[co] = bb[co] - m[co] * sc;
}

// ---------------------------------------------------------------------------
// Kernel 1: tensor-core GEMM, CTA = [256 co x 64 px], K=256 in 4 chunks of 64.
//   W via direct uint4 LDG of pre-built A fragments (L1/L2-hot, no smem).
//   X: fp32 LDG -> fp16 pack -> smem double buffer; ONE sync per chunk.
//   Epilogue: bias + SiLU -> fp16 store.
// ---------------------------------------------------------------------------
__global__ void __launch_bounds__(256, 2) gemm_kernel(const float* __restrict__ X)
{
    extern __shared__ uint32_t sm[];
    const int tile = blockIdx.x, b = blockIdx.y;
    const int tileBase = tile * TILE_N;
    const int t = threadIdx.x, lane = t & 31, warp = t >> 5;   // warp = warpM 0..7
    const int q = lane >> 2, r = lane & 3;
    const float* Xb = X + (size_t)b * NC * NHW + tileBase;
    const int kq = t & 31, pg = t >> 5;       // X staging: kpair 0..31, px grp 0..7

    const uint32_t smBase = (uint32_t)__cvta_generic_to_shared(sm);
    const uint32_t bOff = (uint32_t)((((lane & 16) ? 8 : 0) + (lane & 7)) * 20
                                     + ((lane & 8) ? 4 : 0));

    float acc[2][8][4];
    #pragma unroll
    for (int i = 0; i < 2; i++)
        #pragma unroll
        for (int j = 0; j < 8; j++)
            #pragma unroll
            for (int k = 0; k < 4; k++) acc[i][j][k] = 0.f;

    float4 xr0, xr1, xr2, xr3;

    auto ldgX = [&](int c) {
        const float* x0 = Xb + (size_t)(c * 64 + 2 * kq) * NHW + pg * 8;
        xr0 = *(const float4*)x0;         xr1 = *(const float4*)(x0 + 4);
        xr2 = *(const float4*)(x0 + NHW); xr3 = *(const float4*)(x0 + NHW + 4);
    };
    auto stsX = [&](int sx) {
        float e0[8] = {xr0.x, xr0.y, xr0.z, xr0.w, xr1.x, xr1.y, xr1.z, xr1.w};
        float e1[8] = {xr2.x, xr2.y, xr2.z, xr2.w, xr3.x, xr3.y, xr3.z, xr3.w};
        const int base = sx * 2560 + (kq >> 4) * 1280;
        const int kpc = kq & 15;
        #pragma unroll
        for (int j = 0; j < 8; j++) {
            sm[base + (pg * 8 + j) * 20 + kpc] =
                packh(__float2half_rn(e0[j]), __float2half_rn(e1[j]));
        }
    };

    // per-warp A-fragment base (u32 index): tiles (warp*2 + mt)*16 + kb
    const uint32_t wfBase = (uint32_t)(warp * 2 * 16 * 128 + lane * 4);

    // ---- prologue ----
    ldgX(0);
    stsX(0);
    ldgX(1);
    __syncthreads();

    for (int c = 0; c < 4; c++) {
        if (c < 3) stsX((c + 1) & 1);      // other stage: no hazard with compute
        if (c < 2) ldgX(c + 2);

        const uint32_t xStgBase = smBase + (uint32_t)((c & 1) * 2560) * 4u;
        #pragma unroll
        for (int sub = 0; sub < 2; sub++) {
            const uint32_t xhS = xStgBase + (uint32_t)(sub * 1280) * 4u;
            #pragma unroll
            for (int ks = 0; ks < 2; ks++) {
                const int kb = c * 4 + sub * 2 + ks;
                uint4 A0 = *(const uint4*)&g_wfragA[wfBase + (0 * 16 + kb) * 128];
                uint4 A1 = *(const uint4*)&g_wfragA[wfBase + (1 * 16 + kb) * 128];
                #pragma unroll
                for (int np = 0; np < 4; np++) {
                    uint32_t B0[4];
                    ldsm4(B0, xhS + (bOff + np * 320 + ks * 8) * 4u);
                    #pragma unroll
                    for (int j = 0; j < 2; j++) {
                        mma16816h(acc[0][np * 2 + j], A0.x, A0.y, A0.z, A0.w,
                                  B0[2 * j], B0[2 * j + 1]);
                        mma16816h(acc[1][np * 2 + j], A1.x, A1.y, A1.z, A1.w,
                                  B0[2 * j], B0[2 * j + 1]);
                    }
                }
            }
        }
        __syncthreads();
    }

    // ---- epilogue: bias + SiLU + fp16 store ----
    #pragma unroll
    for (int mt = 0; mt < 2; mt++) {
        const int co0 = warp * 32 + mt * 16 + q;
        const int co1 = co0 + 8;
        const float tb0 = g_bias[co0], tb1 = g_bias[co1];
        __half* y0 = g_xalh + ((size_t)b * NC + co0) * NHW + tileBase;
        __half* y1 = g_xalh + ((size_t)b * NC + co1) * NHW + tileBase;
        #pragma unroll
        for (int nt = 0; nt < 8; nt++) {
            const int pix = nt * 8 + 2 * r;
            float v0 = acc[mt][nt][0] + tb0, v1 = acc[mt][nt][1] + tb0;
            float v2 = acc[mt][nt][2] + tb1, v3 = acc[mt][nt][3] + tb1;
            *(__half2*)&y0[pix] =
                __floats2half2_rn(v0 * sigmoidf_(v0), v1 * sigmoidf_(v1));
            *(__half2*)&y1[pix] =
                __floats2half2_rn(v2 * sigmoidf_(v2), v3 * sigmoidf_(v3));
        }
    }
}

// ---------------------------------------------------------------------------
// Kernel 2: per-(b,c) global sum/max + 4x4 local pool sums (fp16 input)
// ---------------------------------------------------------------------------
__global__ __launch_bounds__(160) void pool_kernel() {
    const int bc = blockIdx.x;
    const __half* plane = g_xalh + (size_t)bc * NHW;
    const int t = threadIdx.x, wb = t & 3, hr = t >> 2;

    float cell[4];
    float gmx = -1e30f;
    #pragma unroll
    for (int gy = 0; gy < 4; gy++) {
        const uint4* rp = (const uint4*)(plane + (gy * 40 + hr) * NW + wb * 40);
        float s = 0.f;
        #pragma unroll
        for (int i = 0; i < 5; i++) {           // 5 x 8 halves = 40
            uint4 v = rp[i];
            float2 f0 = h2f2(v.x), f1 = h2f2(v.y), f2 = h2f2(v.z), f3 = h2f2(v.w);
            s += (f0.x + f0.y) + (f1.x + f1.y) + (f2.x + f2.y) + (f3.x + f3.y);
            gmx = fmaxf(gmx, fmaxf(fmaxf(fmaxf(f0.x, f0.y), fmaxf(f1.x, f1.y)),
                                   fmaxf(fmaxf(f2.x, f2.y), fmaxf(f3.x, f3.y))));
        }
        cell[gy] = s;
    }
    float gs = (cell[0] + cell[1]) + (cell[2] + cell[3]);

    #pragma unroll
    for (int o = 4; o <= 16; o <<= 1)
        #pragma unroll
        for (int gy = 0; gy < 4; gy++)
            cell[gy] += __shfl_xor_sync(0xffffffffu, cell[gy], o);
    #pragma unroll
    for (int o = 1; o <= 16; o <<= 1) {
        gs += __shfl_xor_sync(0xffffffffu, gs, o);
        gmx = fmaxf(gmx, __shfl_xor_sync(0xffffffffu, gmx, o));
    }

    __shared__ float sC[5][4][4], sS[5], sM[5];
    const int w = t >> 5, lanei = t & 31;
    if (lanei < 4) {
        #pragma unroll
        for (int gy = 0; gy < 4; gy++) sC[w][gy][lanei] = cell[gy];
    }
    if (lanei == 0) { sS[w] = gs; sM[w] = gmx; }
    __syncthreads();
    if (t < 16) {
        float v = 0.f;
        #pragma unroll
        for (int w2 = 0; w2 < 5; w2++) v += sC[w2][t >> 2][t & 3];
        g_lsum[bc * 16 + t] = v;
    }
    if (t == 0) {
        float S = 0.f, M = -1e30f;
        #pragma unroll
        for (int w2 = 0; w2 < 5; w2++) { S += sS[w2]; M = fmaxf(M, sM[w2]); }
        g_gsum[bc] = S;
        g_gmax[bc] = M;
    }
}

// ---------------------------------------------------------------------------
// Kernel 3: pre-average offset conv2 weights over the 49 output taps
// ---------------------------------------------------------------------------
__global__ void prep_kernel(const float* __restrict__ off_w2,
                            const float* __restrict__ off_b2) {
    const int i = threadIdx.x;
    if (i < 288) {
        const int d = i / 144, rest = i % 144;
        float s = 0.f;
        for (int j = 0; j < 49; j++) s += off_w2[(d * 49 + j) * 144 + rest];
        g_wavg[i] = s * (1.f / 49.f);
    }
    if (i < 2) {
        float s = 0.f;
        for (int j = 0; j < 49; j++) s += off_b2[i * 49 + j];
        g_bavg[i] = s * (1.f / 49.f);
    }
}

// ---------------------------------------------------------------------------
// Kernel 4: channel attention -> g_ca
// ---------------------------------------------------------------------------
__global__ __launch_bounds__(256) void ca_kernel(
    const float* __restrict__ mlp_w1, const float* __restrict__ mlp_w2,
    const float* __restrict__ loc_w1, const float* __restrict__ loc_w2,
    const float* __restrict__ fusion_w)
{
    const int b = blockIdx.x, tid = threadIdx.x;
    __shared__ float avg[256], mxv[256];
    __shared__ float h1[32], hpart[32][8], hcell[16][16], hbar[16];

    avg[tid] = g_gsum[b * NC + tid] * (1.f / (float)NHW);
    mxv[tid] = g_gmax[b * NC + tid];
    __syncthreads();

    {
        const int m = tid >> 3, part = tid & 7;
        const int mm = m & 15;
        const float* src = (m < 16) ? avg : mxv;
        float a = 0.f;
        #pragma unroll 8
        for (int c = part * 32; c < part * 32 + 32; c++)
            a += mlp_w1[mm * NC + c] * src[c];
        hpart[m][part] = a;
    }
    {
        const int cell = tid >> 4, m2 = tid & 15;
        float a = 0.f;
        #pragma unroll 8
        for (int c = 0; c < NC; c++)
            a += loc_w1[m2 * NC + c] * g_lsum[(b * NC + c) * 16 + cell];
        hcell[cell][m2] = fmaxf(a * (1.f / 1600.f), 0.f);
    }
    __syncthreads();
    if (tid < 32) {
        float a = 0.f;
        #pragma unroll
        for (int p = 0; p < 8; p++) a += hpart[tid][p];
        h1[tid] = fmaxf(a, 0.f);
    }
    if (tid >= 32 && tid < 48) {
        float s = 0.f;
        #pragma unroll
        for (int cell = 0; cell < 16; cell++) s += hcell[cell][tid - 32];
        hbar[tid - 32] = s * (1.f / 16.f);
    }
    __syncthreads();

    float ga = 0.f, la = 0.f;
    #pragma unroll
    for (int m = 0; m < 16; m++) {
        ga += mlp_w2[tid * 16 + m] * (h1[m] + h1[16 + m]);
        la += loc_w2[tid * 16 + m] * hbar[m];
    }
    const float alpha = sigmoidf_(fusion_w[0]);
    g_ca[b * NC + tid] = sigmoidf_(alpha * ga + (1.f - alpha) * la);
}

// ---------------------------------------------------------------------------
// Kernel 5: sf = [mean_c(ca*x), max_c(ca*x)]  (fp16 input, 4 px / thread)
// ---------------------------------------------------------------------------
__global__ __launch_bounds__(256) void sf_kernel() {
    const int b = blockIdx.y;
    const int p4 = blockIdx.x * 256 + threadIdx.x;       // 0..6399
    const __half* xb = g_xalh + (size_t)b * NC * NHW;
    const float* cab = g_ca + b * NC;
    float4 s = make_float4(0.f, 0.f, 0.f, 0.f);
    float4 mx = make_float4(-1e30f, -1e30f, -1e30f, -1e30f);
    #pragma unroll 4
    for (int c = 0; c < NC; c++) {
        const float cc = cab[c];
        uint2 u = *(const uint2*)(xb + (size_t)c * NHW + p4 * 4);
        float2 f0 = h2f2(u.x), f1 = h2f2(u.y);
        float v0 = cc * f0.x, v1 = cc * f0.y, v2 = cc * f1.x, v3 = cc * f1.y;
        s.x += v0; s.y += v1; s.z += v2; s.w += v3;
        mx.x = fmaxf(mx.x, v0); mx.y = fmaxf(mx.y, v1);
        mx.z = fmaxf(mx.z, v2); mx.w = fmaxf(mx.w, v3);
    }
    const float inv = 1.f / (float)NC;
    s.x *= inv; s.y *= inv; s.z *= inv; s.w *= inv;
    ((float4*)(g_sf + (size_t)b * 2 * NHW))[p4] = s;
    ((float4*)(g_sf + (size_t)b * 2 * NHW + NHW))[p4] = mx;
}

// ---------------------------------------------------------------------------
// Kernel 6: offset conv1: 3x3, 2->16 + BN + ReLU
// ---------------------------------------------------------------------------
__global__ __launch_bounds__(256) void off1_kernel(
    const float* __restrict__ w1, const float* __restrict__ gg,
    const float* __restrict__ bt, const float* __restrict__ mm,
    const float* __restrict__ vv)
{
    const int p = blockIdx.x * blockDim.x + threadIdx.x;
    const int co = blockIdx.y, b = blockIdx.z;
    const int h = p / NW, w = p % NW;
    const float* sfb = g_sf + (size_t)b * 2 * NHW;
    float acc = 0.f;
    #pragma unroll
    for (int ci = 0; ci < 2; ci++) {
        #pragma unroll
        for (int ky = 0; ky < 3; ky++) {
            const int hy = h + ky - 1;
            if (hy < 0 || hy >= NH) continue;
            #pragma unroll
            for (int kx = 0; kx < 3; kx++) {
                const int wx = w + kx - 1;
                if (wx < 0 || wx >= NW) continue;
                acc += w1[((co * 2 + ci) * 3 + ky) * 3 + kx] *
                       sfb[ci * NHW + hy * NW + wx];
            }
        }
    }
    const float sc = gg[co] * rsqrtf(vv[co] + BN_EPS);
    const float tb = bt[co] - mm[co] * sc;
    g_o1[((size_t)b * 16 + co) * NHW + p] = fmaxf(acc * sc + tb, 0.f);
}

// ---------------------------------------------------------------------------
// Kernel 7: averaged offset conv2 + tanh*0.5 + grid + bilinear sample
// ---------------------------------------------------------------------------
__global__ __launch_bounds__(256) void off2_sample_kernel() {
    const int b = blockIdx.y;
    const int p = blockIdx.x * blockDim.x + threadIdx.x;
    const int h = p / NW, w = p % NW;
    const float* o1b = g_o1 + (size_t)b * 16 * NHW;

    float off[2];
    #pragma unroll
    for (int d = 0; d < 2; d++) {
        float acc = g_bavg[d];
        for (int ci = 0; ci < 16; ci++) {
            #pragma unroll
            for (int ky = 0; ky < 3; ky++) {
                const int hy = h + ky - 1;
                if (hy < 0 || hy >= NH) continue;
                #pragma unroll
                for (int kx = 0; kx < 3; kx++) {
                    const int wx = w + kx - 1;
                    if (wx < 0 || wx >= NW) continue;
                    acc += g_wavg[(d * 16 + ci) * 9 + ky * 3 + kx] *
                           o1b[(size_t)ci * NHW + hy * NW + wx];
                }
            }
        }
        off[d] = tanhf(acc) * 0.5f;
    }

    const float bx = -1.f + 2.f * (float)w / 159.f;
    const float by = -1.f + 2.f * (float)h / 159.f;
    const float gx = fminf(fmaxf(bx + off[0], -1.f), 1.f);
    const float gy = fminf(fmaxf(by + off[1], -1.f), 1.f);

    const float fx = (gx + 1.f) * ((float)NW * 0.5f) - 0.5f;
    const float fy = (gy + 1.f) * ((float)NH * 0.5f) - 0.5f;
    const float x0f = floorf(fx), y0f = floorf(fy);
    const int x0 = (int)x0f, y0 = (int)y0f;
    const float wx = fx - x0f, wy = fy - y0f;

    const float* sfb = g_sf + (size_t)b * 2 * NHW;
    float out0 = 0.f, out1 = 0.f;
    #pragma unroll
    for (int dy = 0; dy < 2; dy++) {
        const int yy = y0 + dy;
        if (yy < 0 || yy >= NH) continue;
        const float wgy = dy ? wy : (1.f - wy);
        #pragma unroll
        for (int dx = 0; dx < 2; dx++) {
            const int xx = x0 + dx;
            if (xx < 0 || xx >= NW) continue;
            const float wt = wgy * (dx ? wx : (1.f - wx));
            out0 += wt * sfb[yy * NW + xx];
            out1 += wt * sfb[NHW + yy * NW + xx];
        }
    }
    g_sampled[(size_t)b * 2 * NHW + p] = out0;
    g_sampled[(size_t)b * 2 * NHW + NHW + p] = out1;
}

// ---------------------------------------------------------------------------
// Kernel 8: 7x7 conv (2->1) over sampled + sigmoid -> g_sa
// ---------------------------------------------------------------------------
__global__ __launch_bounds__(256) void sa_kernel(const float* __restrict__ attn_w) {
    const int b = blockIdx.y;
    const int p = blockIdx.x * blockDim.x + threadIdx.x;
    const int h = p / NW, w = p % NW;
    const float* sm = g_sampled + (size_t)b * 2 * NHW;
    float acc = 0.f;
    #pragma unroll
    for (int ci = 0; ci < 2; ci++) {
        #pragma unroll
        for (int ky = 0; ky < 7; ky++) {
            const int hy = h + ky - 3;
            if (hy < 0 || hy >= NH) continue;
            #pragma unroll
            for (int kx = 0; kx < 7; kx++) {
                const int wx = w + kx - 3;
                if (wx < 0 || wx >= NW) continue;
                acc += attn_w[(ci * 7 + ky) * 7 + kx] *
                       sm[ci * NHW + hy * NW + wx];
            }
        }
    }
    g_sa[b * NHW + p] = sigmoidf_(acc);
}

// ---------------------------------------------------------------------------
// Kernel 9: out = sa * ca * x_aligned  (fp16 xal, 4 elems / thread)
// ---------------------------------------------------------------------------
__global__ __launch_bounds__(256) void final_kernel(float* __restrict__ out) {
    const unsigned idx4 = blockIdx.x * blockDim.x + threadIdx.x;
    const unsigned total4 = (unsigned)NB * NC * NHW / 4;
    if (idx4 >= total4) return;
    const unsigned e = idx4 * 4;
    const unsigned p = e % NHW;
    const unsigned c = (e / NHW) % NC;
    const unsigned b = e / (NHW * NC);
    uint2 u = *(const uint2*)(g_xalh + e);
    float2 f0 = h2f2(u.x), f1 = h2f2(u.y);
    const float4 sav = *reinterpret_cast<const float4*>(&g_sa[b * NHW + p]);
    const float cc = g_ca[b * NC + c];
    float4 r;
    r.x = f0.x * sav.x * cc;
    r.y = f0.y * sav.y * cc;
    r.z = f1.x * sav.z * cc;
    r.w = f1.y * sav.w * cc;
    *reinterpret_cast<float4*>(&out[e]) = r;
}

// ---------------------------------------------------------------------------
extern "C" void kernel_launch(void* const* d_in, const int* in_sizes, int n_in,
                              void* d_out, int out_size) {
    const float* x       = (const float*)d_in[0];
    const float* align_w = (const float*)d_in[1];
    const float* align_g = (const float*)d_in[2];
    const float* align_b = (const float*)d_in[3];
    const float* align_m = (const float*)d_in[4];
    const float* align_v = (const float*)d_in[5];
    const float* mlp_w1  = (const float*)d_in[6];
    const float* mlp_w2  = (const float*)d_in[7];
    const float* loc_w1  = (const float*)d_in[8];
    const float* loc_w2  = (const float*)d_in[9];
    const float* fusion  = (const float*)d_in[10];
    const float* off_w1  = (const float*)d_in[11];
    const float* off_g   = (const float*)d_in[12];
    const float* off_bt  = (const float*)d_in[13];
    const float* off_m   = (const float*)d_in[14];
    const float* off_v   = (const float*)d_in[15];
    const float* off_w2  = (const float*)d_in[16];
    const float* off_b2  = (const float*)d_in[17];
    const float* attn_w  = (const float*)d_in[18];
    float* out = (float*)d_out;

    wpack_kernel<<<128, 256>>>(align_w, align_g, align_b, align_m, align_v);
    prep_kernel<<<1, 288>>>(off_w2, off_b2);

    dim3 gGemm(NTILES, NB);
    gemm_kernel<<<gGemm, 256, DSMEM_U32 * 4>>>(x);

    pool_kernel<<<NB * NC, 160>>>();
    ca_kernel<<<NB, 256>>>(mlp_w1, mlp_w2, loc_w1, loc_w2, fusion);

    dim3 gPix4(NHW / 4 / 256, NB);
    sf_kernel<<<gPix4, 256>>>();

    dim3 gPix(NHW / 256, NB);
    dim3 gOff1(NHW / 256, 16, NB);
    off1_kernel<<<gOff1, 256>>>(off_w1, off_g, off_bt, off_m, off_v);
    off2_sample_kernel<<<gPix, 256>>>();
    sa_kernel<<<gPix, 256>>>(attn_w);

    const unsigned total4 = (unsigned)NB * NC * NHW / 4;
    final_kernel<<<(total4 + 255) / 256, 256>>>(out);
}